// round 4
// baseline (speedup 1.0000x reference)
#include <cuda_runtime.h>
#include <math.h>

namespace {
constexpr int NB = 72;
constexpr int SS = 512;
constexpr int HH = 768;
constexpr int NG = 8;
constexpr int SN = 9;
constexpr float TEMP_ = 0.07f;
constexpr float AVG_EPS_ = 1e-6f;
constexpr float COS_EPS_ = 1e-8f;
constexpr int VR = 2;
constexpr int SPLITS = 4;           // s-split for fused streaming pass
constexpr int SCHUNK = SS / SPLITS; // 128
}

// Scratch (no allocations allowed)
__device__ float g_mask[3][NB * SS];
__device__ float g_msum[3][NB];
__device__ float g_self[3][NB * HH];
__device__ float g_alpha[3][NB * SS];
__device__ float g_cross[3][NB * HH];
__device__ float g_logits[3][NB];

// packed f32x2 fma: d = a*b + d  (two independent fp32 FMAs)
__device__ __forceinline__ void ffma2(float2& d, const float2& a, const float2& b) {
    unsigned long long& dd = reinterpret_cast<unsigned long long&>(d);
    const unsigned long long& aa = reinterpret_cast<const unsigned long long&>(a);
    const unsigned long long& bb = reinterpret_cast<const unsigned long long&>(b);
    asm("fma.rn.f32x2 %0, %1, %2, %0;" : "+l"(dd) : "l"(aa), "l"(bb));
}

// ---------------------------------------------------------------------------
// Kernel 0: masks + mask sums; zero alpha, self, cross.
// ---------------------------------------------------------------------------
__global__ void k0_masks(const float* __restrict__ am,
                         const int* __restrict__ qa) {
    const int b = blockIdx.x;
    const int tid = threadIdx.x;
    __shared__ float red[3][8];

    float pq = 0.f, pa = 0.f, pn = 0.f;
    for (int s = tid; s < SS; s += blockDim.x) {
        int q = qa[b * SS + s];
        float a = am[b * SS + s];
        float mq = (q == 1 || q == 2) ? a : 0.f;
        float ma = (q == 0 || q == 2) ? a : 0.f;
        float mn = (q == 3) ? a : 0.f;
        g_mask[0][b * SS + s] = mq;
        g_mask[1][b * SS + s] = ma;
        g_mask[2][b * SS + s] = mn;
        g_alpha[0][b * SS + s] = 0.f;
        g_alpha[1][b * SS + s] = 0.f;
        g_alpha[2][b * SS + s] = 0.f;
        pq += mq; pa += ma; pn += mn;
    }
    for (int h = tid; h < HH; h += blockDim.x) {
        #pragma unroll
        for (int m = 0; m < 3; m++) {
            g_self[m][b * HH + h] = 0.f;
            g_cross[m][b * HH + h] = 0.f;
        }
    }
    #pragma unroll
    for (int o = 16; o > 0; o >>= 1) {
        pq += __shfl_down_sync(0xffffffffu, pq, o);
        pa += __shfl_down_sync(0xffffffffu, pa, o);
        pn += __shfl_down_sync(0xffffffffu, pn, o);
    }
    if ((tid & 31) == 0) {
        int w = tid >> 5;
        red[0][w] = pq; red[1][w] = pa; red[2][w] = pn;
    }
    __syncthreads();
    if (tid == 0) {
        int nw = blockDim.x >> 5;
        float s0 = 0.f, s1 = 0.f, s2 = 0.f;
        for (int w = 0; w < nw; w++) { s0 += red[0][w]; s1 += red[1][w]; s2 += red[2][w]; }
        g_msum[0][b] = s0; g_msum[1][b] = s1; g_msum[2][b] = s2;
    }
}

// ---------------------------------------------------------------------------
// Kernel 2: banded symmetric Gram + alpha accumulation (FFMA2 inner loop).
// ---------------------------------------------------------------------------
__global__ void __launch_bounds__(256) k2_gram(const float* __restrict__ x,
                                               const int* __restrict__ turn) {
    const int b = blockIdx.z;
    const int I = blockIdx.y, J = blockIdx.x;
    if (J < I) return;
    const int s0 = I * 64, t0 = J * 64;
    const int* tb = turn + b * SS;
    if (tb[t0] - tb[s0 + 63] > VR) return;
    const bool diag = (I == J);
    const int tid = threadIdx.x;
    const int tx = tid & 15, ty = tid >> 4;

    __shared__ __align__(16) float As[2][32][68];
    __shared__ __align__(16) float Bs[2][32][68];
    __shared__ float sW[2][3][64];
    __shared__ float sM[2][3][64];
    __shared__ int   sT[2][64];
    __shared__ float accT[3][64];
    __shared__ float accS[3][64];

    if (tid < 128) {
        int side = tid >> 6, i = tid & 63;
        int tok = (side ? t0 : s0) + i;
        float mq = g_mask[0][b * SS + tok];
        float ma = g_mask[1][b * SS + tok];
        float mn = g_mask[2][b * SS + tok];
        sM[side][0][i] = mq; sM[side][1][i] = ma; sM[side][2][i] = mn;
        sW[side][0][i] = ma + mn;
        sW[side][1][i] = mq + mn;
        sW[side][2][i] = mq + ma;
        sT[side][i] = tb[tok];
    }
    if (tid < 64) {
        #pragma unroll
        for (int m = 0; m < 3; m++) { accT[m][tid] = 0.f; accS[m][tid] = 0.f; }
    }

    // acc2[ip][j]: rows (4*ty + 2*ip, 4*ty + 2*ip + 1) x col (4*tx + j)
    float2 acc2[2][4];
    #pragma unroll
    for (int ip = 0; ip < 2; ip++)
        #pragma unroll
        for (int j = 0; j < 4; j++) acc2[ip][j] = make_float2(0.f, 0.f);

    const float4* xa  = (const float4*)(x + ((size_t)b * SS + s0) * HH);
    const float4* xbp = (const float4*)(x + ((size_t)b * SS + t0) * HH);
    auto gidx_i  = [&](int l) { int idx = tid + l * 256; return idx >> 3; };
    auto gidx_c4 = [&](int l) { int idx = tid + l * 256; return idx & 7; };

    float4 pa[2], pb[2];
    #pragma unroll
    for (int l = 0; l < 2; l++) {
        int i = gidx_i(l), c4 = gidx_c4(l);
        pa[l] = xa [(size_t)i * (HH / 4) + c4];
        pb[l] = xbp[(size_t)i * (HH / 4) + c4];
    }
    #pragma unroll
    for (int l = 0; l < 2; l++) {
        int i = gidx_i(l), c4 = gidx_c4(l);
        As[0][4 * c4 + 0][i] = pa[l].x; As[0][4 * c4 + 1][i] = pa[l].y;
        As[0][4 * c4 + 2][i] = pa[l].z; As[0][4 * c4 + 3][i] = pa[l].w;
        Bs[0][4 * c4 + 0][i] = pb[l].x; Bs[0][4 * c4 + 1][i] = pb[l].y;
        Bs[0][4 * c4 + 2][i] = pb[l].z; Bs[0][4 * c4 + 3][i] = pb[l].w;
    }
    __syncthreads();

    constexpr int KSTEPS = HH / 32;
    for (int step = 0; step < KSTEPS; step++) {
        const int cur = step & 1;
        const int nxt = step + 1;
        if (nxt < KSTEPS) {
            #pragma unroll
            for (int l = 0; l < 2; l++) {
                int i = gidx_i(l), c4 = gidx_c4(l);
                pa[l] = xa [(size_t)i * (HH / 4) + nxt * 8 + c4];
                pb[l] = xbp[(size_t)i * (HH / 4) + nxt * 8 + c4];
            }
        }
        #pragma unroll
        for (int kk = 0; kk < 32; kk++) {
            float4 a  = *(const float4*)&As[cur][kk][4 * ty];
            float4 bv = *(const float4*)&Bs[cur][kk][4 * tx];
            float2 ap0 = make_float2(a.x, a.y);
            float2 ap1 = make_float2(a.z, a.w);
            float2 b0 = make_float2(bv.x, bv.x);
            float2 b1 = make_float2(bv.y, bv.y);
            float2 b2 = make_float2(bv.z, bv.z);
            float2 b3 = make_float2(bv.w, bv.w);
            ffma2(acc2[0][0], ap0, b0); ffma2(acc2[0][1], ap0, b1);
            ffma2(acc2[0][2], ap0, b2); ffma2(acc2[0][3], ap0, b3);
            ffma2(acc2[1][0], ap1, b0); ffma2(acc2[1][1], ap1, b1);
            ffma2(acc2[1][2], ap1, b2); ffma2(acc2[1][3], ap1, b3);
        }
        if (nxt < KSTEPS) {
            const int nb_ = nxt & 1;
            #pragma unroll
            for (int l = 0; l < 2; l++) {
                int i = gidx_i(l), c4 = gidx_c4(l);
                As[nb_][4 * c4 + 0][i] = pa[l].x; As[nb_][4 * c4 + 1][i] = pa[l].y;
                As[nb_][4 * c4 + 2][i] = pa[l].z; As[nb_][4 * c4 + 3][i] = pa[l].w;
                Bs[nb_][4 * c4 + 0][i] = pb[l].x; Bs[nb_][4 * c4 + 1][i] = pb[l].y;
                Bs[nb_][4 * c4 + 2][i] = pb[l].z; Bs[nb_][4 * c4 + 3][i] = pb[l].w;
            }
        }
        __syncthreads();
    }

    // unpack: acc[di][dj], di = 2*ip + (x:0, y:1)
    float acc[4][4];
    #pragma unroll
    for (int ip = 0; ip < 2; ip++)
        #pragma unroll
        for (int j = 0; j < 4; j++) {
            acc[2 * ip + 0][j] = acc2[ip][j].x;
            acc[2 * ip + 1][j] = acc2[ip][j].y;
        }

    float cq[4], ca_[4], cn_[4], dq[4], da_[4], dn_[4];
    #pragma unroll
    for (int j = 0; j < 4; j++) { cq[j]=0.f; ca_[j]=0.f; cn_[j]=0.f; dq[j]=0.f; da_[j]=0.f; dn_[j]=0.f; }

    #pragma unroll
    for (int di = 0; di < 4; di++) {
        int sl = 4 * ty + di;
        int ts_ = sT[0][sl];
        float mqs = sM[0][0][sl], mas = sM[0][1][sl], mns = sM[0][2][sl];
        float wqs = sW[0][0][sl], was = sW[0][1][sl], wns = sW[0][2][sl];
        #pragma unroll
        for (int dj = 0; dj < 4; dj++) {
            int tl = 4 * tx + dj;
            int dt = sT[1][tl] - ts_;
            if (dt < -VR || dt > VR) continue;
            float wqt = sW[1][0][tl], wat = sW[1][1][tl], wnt = sW[1][2][tl];
            float coef = mqs * wqt + mas * wat + mns * wnt;
            float base = coef * acc[di][dj];
            cq[dj]  = fmaf(wqs, base, cq[dj]);
            ca_[dj] = fmaf(was, base, ca_[dj]);
            cn_[dj] = fmaf(wns, base, cn_[dj]);
            dq[di]  = fmaf(wqt, base, dq[di]);
            da_[di] = fmaf(wat, base, da_[di]);
            dn_[di] = fmaf(wnt, base, dn_[di]);
        }
    }
    #pragma unroll
    for (int dj = 0; dj < 4; dj++) {
        int tl = 4 * tx + dj;
        if (cq[dj]  != 0.f) atomicAdd(&accT[0][tl], cq[dj]);
        if (ca_[dj] != 0.f) atomicAdd(&accT[1][tl], ca_[dj]);
        if (cn_[dj] != 0.f) atomicAdd(&accT[2][tl], cn_[dj]);
    }
    if (!diag) {
        #pragma unroll
        for (int di = 0; di < 4; di++) {
            int sl = 4 * ty + di;
            if (dq[di]  != 0.f) atomicAdd(&accS[0][sl], dq[di]);
            if (da_[di] != 0.f) atomicAdd(&accS[1][sl], da_[di]);
            if (dn_[di] != 0.f) atomicAdd(&accS[2][sl], dn_[di]);
        }
    }
    __syncthreads();
    if (tid < 64) {
        #pragma unroll
        for (int m = 0; m < 3; m++) {
            float v = accT[m][tid];
            if (v != 0.f) atomicAdd(&g_alpha[m][b * SS + t0 + tid], v);
            if (!diag) {
                float w = accS[m][tid];
                if (w != 0.f) atomicAdd(&g_alpha[m][b * SS + s0 + tid], w);
            }
        }
    }
}

// ---------------------------------------------------------------------------
// Kernel 3: FUSED self + cross streaming pass, s-split with atomics.
// grid (3 hblk, NB, SPLITS). Partials are pre-scaled by 1/denominator.
// ---------------------------------------------------------------------------
__global__ void __launch_bounds__(256) k3_fused(const float* __restrict__ x) {
    const int b = blockIdx.y;
    const int h = blockIdx.x * 256 + threadIdx.x;
    const int sc = blockIdx.z;
    const int sbase = sc * SCHUNK;
    const int tid = threadIdx.x;

    __shared__ float smq[SCHUNK], sma[SCHUNK], smn[SCHUNK];
    __shared__ float scq[SCHUNK], sca[SCHUNK], scn[SCHUNK];
    for (int s = tid; s < SCHUNK; s += 256) {
        int gs = b * SS + sbase + s;
        float mq = g_mask[0][gs], ma = g_mask[1][gs], mn = g_mask[2][gs];
        smq[s] = mq; sma[s] = ma; smn[s] = mn;
        scq[s] = mq * g_alpha[0][gs];
        sca[s] = ma * g_alpha[1][gs];
        scn[s] = mn * g_alpha[2][gs];
    }
    __syncthreads();

    float m0 = g_msum[0][b], m1 = g_msum[1][b], m2 = g_msum[2][b];
    float rsq = 1.f / (m0 + AVG_EPS_);
    float rsa = 1.f / (m1 + AVG_EPS_);
    float rsn = 1.f / (m2 + AVG_EPS_);
    float rcq = 1.f / (m1 + m2 + AVG_EPS_);
    float rca = 1.f / (m0 + m2 + AVG_EPS_);
    float rcn = 1.f / (m0 + m1 + AVG_EPS_);

    const float* xb = x + ((size_t)b * SS + sbase) * HH + h;
    float aq = 0.f, aa = 0.f, an = 0.f;   // self
    float bq = 0.f, ba = 0.f, bn = 0.f;   // cross
    #pragma unroll 4
    for (int s = 0; s < SCHUNK; s++) {
        float v = xb[(size_t)s * HH];
        aq = fmaf(smq[s], v, aq);
        aa = fmaf(sma[s], v, aa);
        an = fmaf(smn[s], v, an);
        bq = fmaf(scq[s], v, bq);
        ba = fmaf(sca[s], v, ba);
        bn = fmaf(scn[s], v, bn);
    }
    atomicAdd(&g_self[0][b * HH + h], aq * rsq);
    atomicAdd(&g_self[1][b * HH + h], aa * rsa);
    atomicAdd(&g_self[2][b * HH + h], an * rsn);
    atomicAdd(&g_cross[0][b * HH + h], bq * rcq);
    atomicAdd(&g_cross[1][b * HH + h], ba * rca);
    atomicAdd(&g_cross[2][b * HH + h], bn * rcn);
}

// ---------------------------------------------------------------------------
// Kernel 4: per-batch cosine logits; write q/a/n_output rows.
// ---------------------------------------------------------------------------
__global__ void k4_logits(float* __restrict__ out) {
    const int b = blockIdx.x;
    const int tid = threadIdx.x;
    float p[9];
    #pragma unroll
    for (int k = 0; k < 9; k++) p[k] = 0.f;
    for (int h = tid; h < HH; h += blockDim.x) {
        #pragma unroll
        for (int m = 0; m < 3; m++) {
            float sv = g_self[m][b * HH + h];
            float cv = g_cross[m][b * HH + h];
            p[m * 3 + 0] = fmaf(sv, cv, p[m * 3 + 0]);
            p[m * 3 + 1] = fmaf(sv, sv, p[m * 3 + 1]);
            p[m * 3 + 2] = fmaf(cv, cv, p[m * 3 + 2]);
        }
    }
    #pragma unroll
    for (int k = 0; k < 9; k++)
        #pragma unroll
        for (int o = 16; o > 0; o >>= 1)
            p[k] += __shfl_down_sync(0xffffffffu, p[k], o);
    __shared__ float red[9][8];
    if ((tid & 31) == 0) {
        int w = tid >> 5;
        #pragma unroll
        for (int k = 0; k < 9; k++) red[k][w] = p[k];
    }
    __syncthreads();
    if (tid == 0) {
        #pragma unroll
        for (int m = 0; m < 3; m++) {
            float dot = 0.f, n1 = 0.f, n2 = 0.f;
            for (int w = 0; w < 8; w++) {
                dot += red[m * 3 + 0][w];
                n1  += red[m * 3 + 1][w];
                n2  += red[m * 3 + 2][w];
            }
            float nx = fmaxf(sqrtf(n1), COS_EPS_);
            float ny = fmaxf(sqrtf(n2), COS_EPS_);
            float c = dot / (nx * ny);
            g_logits[m][b] = (c == 1.0f) ? __int_as_float(0x7fc00000) : c / TEMP_;
        }
    }
    if (b % SN == 0) {
        int g = b / SN;
        for (int h = tid; h < HH; h += blockDim.x) {
            out[1 + 0 * NG * HH + g * HH + h] = g_self[0][b * HH + h];
            out[1 + 1 * NG * HH + g * HH + h] = g_self[1][b * HH + h];
            out[1 + 2 * NG * HH + g * HH + h] = g_self[2][b * HH + h];
        }
    }
}

// ---------------------------------------------------------------------------
// Kernel 5: log-softmax + nanmean loss (tiny).
// ---------------------------------------------------------------------------
__global__ void k5_loss(const float* __restrict__ labels, float* __restrict__ out) {
    if (threadIdx.x != 0 || blockIdx.x != 0) return;
    float losses[3];
    for (int m = 0; m < 3; m++) {
        float sum = 0.f;
        int cnt = 0;
        for (int g = 0; g < NG; g++) {
            float l[SN];
            bool bad = false;
            for (int j = 0; j < SN; j++) {
                l[j] = g_logits[m][g * SN + j];
                if (isnan(l[j])) bad = true;
            }
            if (bad) continue;
            float mx = l[0];
            for (int j = 1; j < SN; j++) mx = fmaxf(mx, l[j]);
            float se = 0.f;
            for (int j = 0; j < SN; j++) se += expf(l[j] - mx);
            float lse = mx + logf(se);
            for (int j = 0; j < SN; j++) sum += (l[j] - lse) * labels[g * SN + j];
            cnt += SN;
        }
        losses[m] = -(sum / (float)cnt);
    }
    out[0] = (losses[1] + losses[0] + losses[2]) / 3.0f;
}

// ---------------------------------------------------------------------------
extern "C" void kernel_launch(void* const* d_in, const int* in_sizes, int n_in,
                              void* d_out, int out_size) {
    const float* x      = (const float*)d_in[0];
    const float* am     = (const float*)d_in[1];
    const float* labels = (const float*)d_in[2];
    const int*   qa     = (const int*)d_in[3];
    const int*   turn   = (const int*)d_in[4];
    float* out = (float*)d_out;

    k0_masks<<<NB, 256>>>(am, qa);
    k2_gram<<<dim3(8, 8, NB), 256>>>(x, turn);
    k3_fused<<<dim3(3, NB, SPLITS), 256>>>(x);
    k4_logits<<<NB, 256>>>(out);
    k5_loss<<<1, 32>>>(labels, out);
}

// round 7
// speedup vs baseline: 1.3753x; 1.3753x over previous
#include <cuda_runtime.h>
#include <math.h>
#include <cstdint>

namespace {
constexpr int NB = 72;
constexpr int SS = 512;
constexpr int HH = 768;
constexpr int NG = 8;
constexpr int SN = 9;
constexpr float TEMP_ = 0.07f;
constexpr float AVG_EPS_ = 1e-6f;
constexpr float COS_EPS_ = 1e-8f;
constexpr int VR = 2;
constexpr int SPLITS = 4;
constexpr int SCHUNK = SS / SPLITS;

// ---- gram tiling ----
constexpr int TM = 128, TN = 128, KC = 64;
constexpr int NCHUNK = HH / KC;  // 12

// ---- smem layout for gram kernel ----
constexpr int SM_TURNT = 0;      // int[128] t-side turn
constexpr int SM_TURNS = 512;    // int[128] s-side turn
constexpr int SM_WQT   = 1024;   // t-side w (float[128] each)
constexpr int SM_WAT   = 1536;
constexpr int SM_WNT   = 2048;
constexpr int SM_MQS   = 2560;   // s-side raw masks
constexpr int SM_MAS   = 3072;
constexpr int SM_MNS   = 3584;
constexpr int SM_SWQ   = 4096;   // s-side w
constexpr int SM_SWA   = 4608;
constexpr int SM_SWN   = 5120;
constexpr int SM_STAGE = 6144;   // 64KB stage: A_HI, A_LO, B_HI, B_LO
constexpr int A_HI = 0, A_LO = 16384, B_HI = 32768, B_LO = 49152;
constexpr int WSTRIDE = 129;     // W overlay on stage: 128*129*4 = 66048 B
constexpr int SMEM_BYTES = SM_STAGE + 128 * WSTRIDE * 4;  // 72192
}

// Scratch (no allocations allowed)
__device__ float g_mask[3][NB * SS];
__device__ float g_msum[3][NB];
__device__ float g_self[3][NB * HH];
__device__ float g_alpha[3][NB * SS];
__device__ float g_cross[3][NB * HH];
__device__ float g_logits[3][NB];

// ===================== helpers =====================
__device__ __forceinline__ uint32_t smem_u32(const void* p) {
    uint32_t a;
    asm("{ .reg .u64 t; cvta.to.shared.u64 t, %1; cvt.u32.u64 %0, t; }" : "=r"(a) : "l"(p));
    return a;
}
__device__ __forceinline__ uint32_t swz128(uint32_t off) { return off ^ ((off >> 3) & 0x70); }

__device__ __forceinline__ void ldmx4(uint32_t* r, uint32_t addr) {
    asm volatile("ldmatrix.sync.aligned.m8n8.x4.shared.b16 {%0,%1,%2,%3}, [%4];"
                 : "=r"(r[0]), "=r"(r[1]), "=r"(r[2]), "=r"(r[3]) : "r"(addr));
}
__device__ __forceinline__ void mma16816(float* d, const uint32_t* a, const uint32_t* b) {
    asm volatile(
        "mma.sync.aligned.m16n8k16.row.col.f32.bf16.bf16.f32 "
        "{%0,%1,%2,%3}, {%4,%5,%6,%7}, {%8,%9}, {%0,%1,%2,%3};"
        : "+f"(d[0]), "+f"(d[1]), "+f"(d[2]), "+f"(d[3])
        : "r"(a[0]), "r"(a[1]), "r"(a[2]), "r"(a[3]), "r"(b[0]), "r"(b[1]));
}

// ---------------------------------------------------------------------------
// Kernel 0: masks + mask sums; zero alpha, self, cross.
// ---------------------------------------------------------------------------
__global__ void k0_masks(const float* __restrict__ am,
                         const int* __restrict__ qa) {
    const int b = blockIdx.x;
    const int tid = threadIdx.x;
    __shared__ float red[3][8];

    float pq = 0.f, pa = 0.f, pn = 0.f;
    for (int s = tid; s < SS; s += blockDim.x) {
        int q = qa[b * SS + s];
        float a = am[b * SS + s];
        float mq = (q == 1 || q == 2) ? a : 0.f;
        float ma = (q == 0 || q == 2) ? a : 0.f;
        float mn = (q == 3) ? a : 0.f;
        g_mask[0][b * SS + s] = mq;
        g_mask[1][b * SS + s] = ma;
        g_mask[2][b * SS + s] = mn;
        g_alpha[0][b * SS + s] = 0.f;
        g_alpha[1][b * SS + s] = 0.f;
        g_alpha[2][b * SS + s] = 0.f;
        pq += mq; pa += ma; pn += mn;
    }
    for (int h = tid; h < HH; h += blockDim.x) {
        #pragma unroll
        for (int m = 0; m < 3; m++) {
            g_self[m][b * HH + h] = 0.f;
            g_cross[m][b * HH + h] = 0.f;
        }
    }
    #pragma unroll
    for (int o = 16; o > 0; o >>= 1) {
        pq += __shfl_down_sync(0xffffffffu, pq, o);
        pa += __shfl_down_sync(0xffffffffu, pa, o);
        pn += __shfl_down_sync(0xffffffffu, pn, o);
    }
    if ((tid & 31) == 0) {
        int w = tid >> 5;
        red[0][w] = pq; red[1][w] = pa; red[2][w] = pn;
    }
    __syncthreads();
    if (tid == 0) {
        int nw = blockDim.x >> 5;
        float s0 = 0.f, s1 = 0.f, s2 = 0.f;
        for (int w = 0; w < nw; w++) { s0 += red[0][w]; s1 += red[1][w]; s2 += red[2][w]; }
        g_msum[0][b] = s0; g_msum[1][b] = s1; g_msum[2][b] = s2;
    }
}

// ---------------------------------------------------------------------------
// Kernel 2: banded Gram via mma.sync bf16 hi/lo split (3 passes).
// Full (I,J) grid, band-pruned. 8 warps: 2(M)x4(N), warp tile 64x32.
// ---------------------------------------------------------------------------
__global__ void __launch_bounds__(256, 1)
k2_mma(const float* __restrict__ x, const int* __restrict__ turn) {
    const int b = blockIdx.z;
    const int I = blockIdx.y, J = blockIdx.x;
    const int s0 = I * TM, t0 = J * TN;
    const int* tb = turn + b * SS;
    if (tb[t0] - tb[s0 + TM - 1] > VR) return;
    if (tb[s0] - tb[t0 + TN - 1] > VR) return;

    extern __shared__ char smem[];
    const uint32_t sb = smem_u32(smem);
    const int tid = threadIdx.x, wid = tid >> 5, lane = tid & 31;
    const int wm = wid & 1, wn = wid >> 1;

    int*   turnT = (int*)(smem + SM_TURNT);
    int*   turnS = (int*)(smem + SM_TURNS);
    float* wqT = (float*)(smem + SM_WQT);
    float* waT = (float*)(smem + SM_WAT);
    float* wnT = (float*)(smem + SM_WNT);
    float* mqS = (float*)(smem + SM_MQS);
    float* maS = (float*)(smem + SM_MAS);
    float* mnS = (float*)(smem + SM_MNS);
    float* sWq = (float*)(smem + SM_SWQ);
    float* sWa = (float*)(smem + SM_SWA);
    float* sWn = (float*)(smem + SM_SWN);
    if (tid < 128) {
        int gt = b * SS + t0 + tid;
        float mq = g_mask[0][gt], ma = g_mask[1][gt], mn = g_mask[2][gt];
        wqT[tid] = ma + mn; waT[tid] = mq + mn; wnT[tid] = mq + ma;
        turnT[tid] = tb[t0 + tid];
        int gs = b * SS + s0 + tid;
        float mqs = g_mask[0][gs], mas = g_mask[1][gs], mns = g_mask[2][gs];
        mqS[tid] = mqs; maS[tid] = mas; mnS[tid] = mns;
        sWq[tid] = mas + mns; sWa[tid] = mqs + mns; sWn[tid] = mqs + mas;
        turnS[tid] = tb[s0 + tid];
    }

    float acc[4][4][4];
    #pragma unroll
    for (int mi = 0; mi < 4; mi++)
        #pragma unroll
        for (int ni = 0; ni < 4; ni++)
            #pragma unroll
            for (int e = 0; e < 4; e++) acc[mi][ni][e] = 0.f;

    // per-lane ldmatrix row/k offsets
    const int rA = wm * 64 + (lane & 15);           // + mi*16
    const int kAe = (lane >> 4) * 16;               // byte offset within k16 step
    const int rB = wn * 32 + ((lane >> 4) & 1) * 8 + (lane & 7);  // + nb*16
    const int kBe = ((lane >> 3) & 1) * 16;

    const uint32_t stg = sb + SM_STAGE;

    for (int i = 0; i < NCHUNK; i++) {
        const int k0 = i * KC;
        char* stgp = smem + SM_STAGE;
        // ---- load + fp32->bf16 hi/lo convert + swizzled store ----
        #pragma unroll
        for (int u = 0; u < 8; u++) {
            int unit = tid + u * 256;
            int isB = unit >> 10;
            int loc = unit & 1023;
            int row = loc >> 3, ucol = loc & 7;
            const float* xr = x + ((size_t)b * SS + (isB ? t0 : s0) + row) * HH + k0 + ucol * 8;
            float4 v0 = *(const float4*)xr;
            float4 v1 = *(const float4*)(xr + 4);
            uint32_t i0 = __float_as_uint(v0.x), i1 = __float_as_uint(v0.y);
            uint32_t i2 = __float_as_uint(v0.z), i3 = __float_as_uint(v0.w);
            uint32_t i4 = __float_as_uint(v1.x), i5 = __float_as_uint(v1.y);
            uint32_t i6 = __float_as_uint(v1.z), i7 = __float_as_uint(v1.w);
            uint4 Hi;
            Hi.x = __byte_perm(i0, i1, 0x7632);
            Hi.y = __byte_perm(i2, i3, 0x7632);
            Hi.z = __byte_perm(i4, i5, 0x7632);
            Hi.w = __byte_perm(i6, i7, 0x7632);
            uint32_t l0 = __float_as_uint(v0.x - __uint_as_float(i0 & 0xffff0000u));
            uint32_t l1 = __float_as_uint(v0.y - __uint_as_float(i1 & 0xffff0000u));
            uint32_t l2 = __float_as_uint(v0.z - __uint_as_float(i2 & 0xffff0000u));
            uint32_t l3 = __float_as_uint(v0.w - __uint_as_float(i3 & 0xffff0000u));
            uint32_t l4 = __float_as_uint(v1.x - __uint_as_float(i4 & 0xffff0000u));
            uint32_t l5 = __float_as_uint(v1.y - __uint_as_float(i5 & 0xffff0000u));
            uint32_t l6 = __float_as_uint(v1.z - __uint_as_float(i6 & 0xffff0000u));
            uint32_t l7 = __float_as_uint(v1.w - __uint_as_float(i7 & 0xffff0000u));
            uint4 Lo;
            Lo.x = __byte_perm(l0, l1, 0x7632);
            Lo.y = __byte_perm(l2, l3, 0x7632);
            Lo.z = __byte_perm(l4, l5, 0x7632);
            Lo.w = __byte_perm(l6, l7, 0x7632);
            uint32_t off = swz128((uint32_t)(row * 128 + ucol * 16));
            *(uint4*)(stgp + (isB ? B_HI : A_HI) + off) = Hi;
            *(uint4*)(stgp + (isB ? B_LO : A_LO) + off) = Lo;
        }
        __syncthreads();

        // ---- mma over 4 k16-steps, 3 passes (hi*hi, hi*lo, lo*hi) ----
        #pragma unroll
        for (int kk = 0; kk < 4; kk++) {
            const uint32_t kb = kk * 32;
            uint32_t bh[2][4], bl[2][4];
            #pragma unroll
            for (int nb = 0; nb < 2; nb++) {
                uint32_t roff = (uint32_t)((rB + nb * 16) * 128 + kb + kBe);
                ldmx4(bh[nb], stg + B_HI + swz128(roff));
                ldmx4(bl[nb], stg + B_LO + swz128(roff));
            }
            {
                uint32_t ah[4][4];
                #pragma unroll
                for (int mi = 0; mi < 4; mi++) {
                    uint32_t roff = (uint32_t)((rA + mi * 16) * 128 + kb + kAe);
                    ldmx4(ah[mi], stg + A_HI + swz128(roff));
                }
                #pragma unroll
                for (int mi = 0; mi < 4; mi++)
                    #pragma unroll
                    for (int ni = 0; ni < 4; ni++) {
                        mma16816(acc[mi][ni], ah[mi], &bh[ni >> 1][2 * (ni & 1)]);
                        mma16816(acc[mi][ni], ah[mi], &bl[ni >> 1][2 * (ni & 1)]);
                    }
            }
            {
                uint32_t al[4][4];
                #pragma unroll
                for (int mi = 0; mi < 4; mi++) {
                    uint32_t roff = (uint32_t)((rA + mi * 16) * 128 + kb + kAe);
                    ldmx4(al[mi], stg + A_LO + swz128(roff));
                }
                #pragma unroll
                for (int mi = 0; mi < 4; mi++)
                    #pragma unroll
                    for (int ni = 0; ni < 4; ni++)
                        mma16816(acc[mi][ni], al[mi], &bh[ni >> 1][2 * (ni & 1)]);
            }
        }
        __syncthreads();
    }

    // ---- epilogue: W[s][t] = coef*band*G into smem (overlay on stage) ----
    float* Wb = (float*)(smem + SM_STAGE);
    #pragma unroll
    for (int mi = 0; mi < 4; mi++) {
        int r0 = wm * 64 + mi * 16 + (lane >> 2);
        int r1 = r0 + 8;
        float mq0 = mqS[r0], ma0 = maS[r0], mn0 = mnS[r0];
        float mq1 = mqS[r1], ma1 = maS[r1], mn1 = mnS[r1];
        int tn0 = turnS[r0], tn1 = turnS[r1];
        #pragma unroll
        for (int ni = 0; ni < 4; ni++) {
            int tb0 = wn * 32 + ni * 8 + (lane & 3) * 2;
            #pragma unroll
            for (int e = 0; e < 4; e++) {
                int srow = (e >> 1) ? r1 : r0;
                int tcol = tb0 + (e & 1);
                float mq_ = (e >> 1) ? mq1 : mq0;
                float ma_ = (e >> 1) ? ma1 : ma0;
                float mn_ = (e >> 1) ? mn1 : mn0;
                int tn_ = (e >> 1) ? tn1 : tn0;
                int dt = turnT[tcol] - tn_;
                float coef = fmaf(mq_, wqT[tcol], fmaf(ma_, waT[tcol], mn_ * wnT[tcol]));
                float v = (dt >= -VR && dt <= VR) ? coef * acc[mi][ni][e] : 0.f;
                Wb[srow * WSTRIDE + tcol] = v;
            }
        }
    }
    __syncthreads();
    if (tid < 128) {
        float aq = 0.f, aa = 0.f, an = 0.f;
        #pragma unroll 4
        for (int s = 0; s < 128; s++) {
            float wv = Wb[s * WSTRIDE + tid];
            aq = fmaf(sWq[s], wv, aq);
            aa = fmaf(sWa[s], wv, aa);
            an = fmaf(sWn[s], wv, an);
        }
        atomicAdd(&g_alpha[0][b * SS + t0 + tid], aq);
        atomicAdd(&g_alpha[1][b * SS + t0 + tid], aa);
        atomicAdd(&g_alpha[2][b * SS + t0 + tid], an);
    }
}

// ---------------------------------------------------------------------------
// Kernel 3: FUSED self + cross streaming pass, s-split with atomics.
// ---------------------------------------------------------------------------
__global__ void __launch_bounds__(256) k3_fused(const float* __restrict__ x) {
    const int b = blockIdx.y;
    const int h = blockIdx.x * 256 + threadIdx.x;
    const int sc = blockIdx.z;
    const int sbase = sc * SCHUNK;
    const int tid = threadIdx.x;

    __shared__ float smq[SCHUNK], sma[SCHUNK], smn[SCHUNK];
    __shared__ float scq[SCHUNK], sca[SCHUNK], scn[SCHUNK];
    for (int s = tid; s < SCHUNK; s += 256) {
        int gs = b * SS + sbase + s;
        float mq = g_mask[0][gs], ma = g_mask[1][gs], mn = g_mask[2][gs];
        smq[s] = mq; sma[s] = ma; smn[s] = mn;
        scq[s] = mq * g_alpha[0][gs];
        sca[s] = ma * g_alpha[1][gs];
        scn[s] = mn * g_alpha[2][gs];
    }
    __syncthreads();

    float m0 = g_msum[0][b], m1 = g_msum[1][b], m2 = g_msum[2][b];
    float rsq = 1.f / (m0 + AVG_EPS_);
    float rsa = 1.f / (m1 + AVG_EPS_);
    float rsn = 1.f / (m2 + AVG_EPS_);
    float rcq = 1.f / (m1 + m2 + AVG_EPS_);
    float rca = 1.f / (m0 + m2 + AVG_EPS_);
    float rcn = 1.f / (m0 + m1 + AVG_EPS_);

    const float* xb = x + ((size_t)b * SS + sbase) * HH + h;
    float aq = 0.f, aa = 0.f, an = 0.f;
    float bq = 0.f, ba = 0.f, bn = 0.f;
    #pragma unroll 4
    for (int s = 0; s < SCHUNK; s++) {
        float v = xb[(size_t)s * HH];
        aq = fmaf(smq[s], v, aq);
        aa = fmaf(sma[s], v, aa);
        an = fmaf(smn[s], v, an);
        bq = fmaf(scq[s], v, bq);
        ba = fmaf(sca[s], v, ba);
        bn = fmaf(scn[s], v, bn);
    }
    atomicAdd(&g_self[0][b * HH + h], aq * rsq);
    atomicAdd(&g_self[1][b * HH + h], aa * rsa);
    atomicAdd(&g_self[2][b * HH + h], an * rsn);
    atomicAdd(&g_cross[0][b * HH + h], bq * rcq);
    atomicAdd(&g_cross[1][b * HH + h], ba * rca);
    atomicAdd(&g_cross[2][b * HH + h], bn * rcn);
}

// ---------------------------------------------------------------------------
// Kernel 4: per-batch cosine logits; write q/a/n_output rows.
// ---------------------------------------------------------------------------
__global__ void k4_logits(float* __restrict__ out) {
    const int b = blockIdx.x;
    const int tid = threadIdx.x;
    float p[9];
    #pragma unroll
    for (int k = 0; k < 9; k++) p[k] = 0.f;
    for (int h = tid; h < HH; h += blockDim.x) {
        #pragma unroll
        for (int m = 0; m < 3; m++) {
            float sv = g_self[m][b * HH + h];
            float cv = g_cross[m][b * HH + h];
            p[m * 3 + 0] = fmaf(sv, cv, p[m * 3 + 0]);
            p[m * 3 + 1] = fmaf(sv, sv, p[m * 3 + 1]);
            p[m * 3 + 2] = fmaf(cv, cv, p[m * 3 + 2]);
        }
    }
    #pragma unroll
    for (int k = 0; k < 9; k++)
        #pragma unroll
        for (int o = 16; o > 0; o >>= 1)
            p[k] += __shfl_down_sync(0xffffffffu, p[k], o);
    __shared__ float red[9][8];
    if ((tid & 31) == 0) {
        int w = tid >> 5;
        #pragma unroll
        for (int k = 0; k < 9; k++) red[k][w] = p[k];
    }
    __syncthreads();
    if (tid == 0) {
        #pragma unroll
        for (int m = 0; m < 3; m++) {
            float dot = 0.f, n1 = 0.f, n2 = 0.f;
            for (int w = 0; w < 8; w++) {
                dot += red[m * 3 + 0][w];
                n1  += red[m * 3 + 1][w];
                n2  += red[m * 3 + 2][w];
            }
            float nx = fmaxf(sqrtf(n1), COS_EPS_);
            float ny = fmaxf(sqrtf(n2), COS_EPS_);
            float c = dot / (nx * ny);
            g_logits[m][b] = (c == 1.0f) ? __int_as_float(0x7fc00000) : c / TEMP_;
        }
    }
    if (b % SN == 0) {
        int g = b / SN;
        for (int h = tid; h < HH; h += blockDim.x) {
            out[1 + 0 * NG * HH + g * HH + h] = g_self[0][b * HH + h];
            out[1 + 1 * NG * HH + g * HH + h] = g_self[1][b * HH + h];
            out[1 + 2 * NG * HH + g * HH + h] = g_self[2][b * HH + h];
        }
    }
}

// ---------------------------------------------------------------------------
// Kernel 5: log-softmax + nanmean loss (tiny).
// ---------------------------------------------------------------------------
__global__ void k5_loss(const float* __restrict__ labels, float* __restrict__ out) {
    if (threadIdx.x != 0 || blockIdx.x != 0) return;
    float losses[3];
    for (int m = 0; m < 3; m++) {
        float sum = 0.f;
        int cnt = 0;
        for (int g = 0; g < NG; g++) {
            float l[SN];
            bool bad = false;
            for (int j = 0; j < SN; j++) {
                l[j] = g_logits[m][g * SN + j];
                if (isnan(l[j])) bad = true;
            }
            if (bad) continue;
            float mx = l[0];
            for (int j = 1; j < SN; j++) mx = fmaxf(mx, l[j]);
            float se = 0.f;
            for (int j = 0; j < SN; j++) se += expf(l[j] - mx);
            float lse = mx + logf(se);
            for (int j = 0; j < SN; j++) sum += (l[j] - lse) * labels[g * SN + j];
            cnt += SN;
        }
        losses[m] = -(sum / (float)cnt);
    }
    out[0] = (losses[1] + losses[0] + losses[2]) / 3.0f;
}

// ---------------------------------------------------------------------------
extern "C" void kernel_launch(void* const* d_in, const int* in_sizes, int n_in,
                              void* d_out, int out_size) {
    const float* x      = (const float*)d_in[0];
    const float* am     = (const float*)d_in[1];
    const float* labels = (const float*)d_in[2];
    const int*   qa     = (const int*)d_in[3];
    const int*   turn   = (const int*)d_in[4];
    float* out = (float*)d_out;

    cudaFuncSetAttribute(k2_mma, cudaFuncAttributeMaxDynamicSharedMemorySize, SMEM_BYTES);

    k0_masks<<<NB, 256>>>(am, qa);
    k2_mma<<<dim3(SS / TN, SS / TM, NB), 256, SMEM_BYTES>>>(x, turn);
    k3_fused<<<dim3(3, NB, SPLITS), 256>>>(x);
    k4_logits<<<NB, 256>>>(out);
    k5_loss<<<1, 32>>>(labels, out);
}

// round 8
// speedup vs baseline: 1.8929x; 1.3763x over previous
#include <cuda_runtime.h>
#include <math.h>
#include <cstdint>

namespace {
constexpr int NB = 72;
constexpr int SS = 512;
constexpr int HH = 768;
constexpr int NG = 8;
constexpr int SN = 9;
constexpr float TEMP_ = 0.07f;
constexpr float AVG_EPS_ = 1e-6f;
constexpr float COS_EPS_ = 1e-8f;
constexpr int VR = 2;
constexpr int SPLITS = 8;
constexpr int SCHUNK = SS / SPLITS;  // 64

// ---- gram tiling ----
constexpr int TM = 128, TN = 128, KC = 64;
constexpr int NCHUNK = HH / KC;  // 12

// ---- smem layout for gram kernel ----
constexpr int SM_TURNT = 0;      // int[128]
constexpr int SM_TURNS = 512;
constexpr int SM_WQT   = 1024;   // t-side w
constexpr int SM_WAT   = 1536;
constexpr int SM_WNT   = 2048;
constexpr int SM_MQS   = 2560;   // s-side raw masks
constexpr int SM_MAS   = 3072;
constexpr int SM_MNS   = 3584;
constexpr int SM_SWQ   = 4096;   // s-side w
constexpr int SM_SWA   = 4608;
constexpr int SM_SWN   = 5120;
constexpr int SM_STAGE = 6144;   // 2 x 64KB stage
constexpr int STAGE_BYTES = 65536;
constexpr int A_HI = 0, A_LO = 16384, B_HI = 32768, B_LO = 49152;
constexpr int WSTRIDE = 129;     // W overlay on stage (needs 66048 B <= 128KB)
constexpr int SMEM_BYTES = SM_STAGE + 2 * STAGE_BYTES;  // 137216
}

// Scratch (no allocations allowed)
__device__ float g_mask[3][NB * SS];
__device__ float g_msum[3][NB];
__device__ float g_self[3][NB * HH];
__device__ float g_alpha[3][NB * SS];
__device__ float g_cross[3][NB * HH];
__device__ float g_logits[3][NB];

// ===================== helpers =====================
__device__ __forceinline__ uint32_t smem_u32(const void* p) {
    uint32_t a;
    asm("{ .reg .u64 t; cvta.to.shared.u64 t, %1; cvt.u32.u64 %0, t; }" : "=r"(a) : "l"(p));
    return a;
}
__device__ __forceinline__ uint32_t swz128(uint32_t off) { return off ^ ((off >> 3) & 0x70); }

__device__ __forceinline__ void ldmx4(uint32_t* r, uint32_t addr) {
    asm volatile("ldmatrix.sync.aligned.m8n8.x4.shared.b16 {%0,%1,%2,%3}, [%4];"
                 : "=r"(r[0]), "=r"(r[1]), "=r"(r[2]), "=r"(r[3]) : "r"(addr));
}
__device__ __forceinline__ void mma16816(float* d, const uint32_t* a, const uint32_t* b) {
    asm volatile(
        "mma.sync.aligned.m16n8k16.row.col.f32.bf16.bf16.f32 "
        "{%0,%1,%2,%3}, {%4,%5,%6,%7}, {%8,%9}, {%0,%1,%2,%3};"
        : "+f"(d[0]), "+f"(d[1]), "+f"(d[2]), "+f"(d[3])
        : "r"(a[0]), "r"(a[1]), "r"(a[2]), "r"(a[3]), "r"(b[0]), "r"(b[1]));
}

// convert 2 float4 -> hi/lo bf16x8 and store swizzled
__device__ __forceinline__ void cvt_store(char* stgp, int base, uint32_t off,
                                          const float4& v0, const float4& v1) {
    uint32_t i0 = __float_as_uint(v0.x), i1 = __float_as_uint(v0.y);
    uint32_t i2 = __float_as_uint(v0.z), i3 = __float_as_uint(v0.w);
    uint32_t i4 = __float_as_uint(v1.x), i5 = __float_as_uint(v1.y);
    uint32_t i6 = __float_as_uint(v1.z), i7 = __float_as_uint(v1.w);
    uint4 Hi;
    Hi.x = __byte_perm(i0, i1, 0x7632);
    Hi.y = __byte_perm(i2, i3, 0x7632);
    Hi.z = __byte_perm(i4, i5, 0x7632);
    Hi.w = __byte_perm(i6, i7, 0x7632);
    uint32_t l0 = __float_as_uint(v0.x - __uint_as_float(i0 & 0xffff0000u));
    uint32_t l1 = __float_as_uint(v0.y - __uint_as_float(i1 & 0xffff0000u));
    uint32_t l2 = __float_as_uint(v0.z - __uint_as_float(i2 & 0xffff0000u));
    uint32_t l3 = __float_as_uint(v0.w - __uint_as_float(i3 & 0xffff0000u));
    uint32_t l4 = __float_as_uint(v1.x - __uint_as_float(i4 & 0xffff0000u));
    uint32_t l5 = __float_as_uint(v1.y - __uint_as_float(i5 & 0xffff0000u));
    uint32_t l6 = __float_as_uint(v1.z - __uint_as_float(i6 & 0xffff0000u));
    uint32_t l7 = __float_as_uint(v1.w - __uint_as_float(i7 & 0xffff0000u));
    uint4 Lo;
    Lo.x = __byte_perm(l0, l1, 0x7632);
    Lo.y = __byte_perm(l2, l3, 0x7632);
    Lo.z = __byte_perm(l4, l5, 0x7632);
    Lo.w = __byte_perm(l6, l7, 0x7632);
    *(uint4*)(stgp + base + off) = Hi;
    *(uint4*)(stgp + base + 16384 + off) = Lo;   // LO plane is +16KB from HI plane
}

// ---------------------------------------------------------------------------
// Kernel 0: masks + mask sums; zero alpha, self, cross.
// ---------------------------------------------------------------------------
__global__ void k0_masks(const float* __restrict__ am,
                         const int* __restrict__ qa) {
    const int b = blockIdx.x;
    const int tid = threadIdx.x;
    __shared__ float red[3][8];

    float pq = 0.f, pa = 0.f, pn = 0.f;
    for (int s = tid; s < SS; s += blockDim.x) {
        int q = qa[b * SS + s];
        float a = am[b * SS + s];
        float mq = (q == 1 || q == 2) ? a : 0.f;
        float ma = (q == 0 || q == 2) ? a : 0.f;
        float mn = (q == 3) ? a : 0.f;
        g_mask[0][b * SS + s] = mq;
        g_mask[1][b * SS + s] = ma;
        g_mask[2][b * SS + s] = mn;
        g_alpha[0][b * SS + s] = 0.f;
        g_alpha[1][b * SS + s] = 0.f;
        g_alpha[2][b * SS + s] = 0.f;
        pq += mq; pa += ma; pn += mn;
    }
    for (int h = tid; h < HH; h += blockDim.x) {
        #pragma unroll
        for (int m = 0; m < 3; m++) {
            g_self[m][b * HH + h] = 0.f;
            g_cross[m][b * HH + h] = 0.f;
        }
    }
    #pragma unroll
    for (int o = 16; o > 0; o >>= 1) {
        pq += __shfl_down_sync(0xffffffffu, pq, o);
        pa += __shfl_down_sync(0xffffffffu, pa, o);
        pn += __shfl_down_sync(0xffffffffu, pn, o);
    }
    if ((tid & 31) == 0) {
        int w = tid >> 5;
        red[0][w] = pq; red[1][w] = pa; red[2][w] = pn;
    }
    __syncthreads();
    if (tid == 0) {
        int nw = blockDim.x >> 5;
        float s0 = 0.f, s1 = 0.f, s2 = 0.f;
        for (int w = 0; w < nw; w++) { s0 += red[0][w]; s1 += red[1][w]; s2 += red[2][w]; }
        g_msum[0][b] = s0; g_msum[1][b] = s1; g_msum[2][b] = s2;
    }
}

// ---------------------------------------------------------------------------
// Kernel 2: banded SYMMETRIC Gram via mma.sync bf16 hi/lo (3 passes).
// Upper triangle only (J>=I); dual gemv epilogue mirrors off-diag tiles.
// Double-buffered smem stage with register prefetch.
// ---------------------------------------------------------------------------
__global__ void __launch_bounds__(256, 1)
k2_mma(const float* __restrict__ x, const int* __restrict__ turn) {
    const int b = blockIdx.z;
    const int I = blockIdx.y, J = blockIdx.x;
    if (J < I) return;
    const int s0 = I * TM, t0 = J * TN;
    const int* tb = turn + b * SS;
    if (tb[t0] - tb[s0 + TM - 1] > VR) return;   // sorted turns, J>=I
    const bool diag = (I == J);

    extern __shared__ char smem[];
    const uint32_t sb = smem_u32(smem);
    const int tid = threadIdx.x, wid = tid >> 5, lane = tid & 31;
    const int wm = wid & 1, wn = wid >> 1;

    int*   turnT = (int*)(smem + SM_TURNT);
    int*   turnS = (int*)(smem + SM_TURNS);
    float* wqT = (float*)(smem + SM_WQT);
    float* waT = (float*)(smem + SM_WAT);
    float* wnT = (float*)(smem + SM_WNT);
    float* mqS = (float*)(smem + SM_MQS);
    float* maS = (float*)(smem + SM_MAS);
    float* mnS = (float*)(smem + SM_MNS);
    float* sWq = (float*)(smem + SM_SWQ);
    float* sWa = (float*)(smem + SM_SWA);
    float* sWn = (float*)(smem + SM_SWN);
    if (tid < 128) {
        int gt = b * SS + t0 + tid;
        float mq = g_mask[0][gt], ma = g_mask[1][gt], mn = g_mask[2][gt];
        wqT[tid] = ma + mn; waT[tid] = mq + mn; wnT[tid] = mq + ma;
        turnT[tid] = tb[t0 + tid];
        int gs = b * SS + s0 + tid;
        float mqs = g_mask[0][gs], mas = g_mask[1][gs], mns = g_mask[2][gs];
        mqS[tid] = mqs; maS[tid] = mas; mnS[tid] = mns;
        sWq[tid] = mas + mns; sWa[tid] = mqs + mns; sWn[tid] = mqs + mas;
        turnS[tid] = tb[s0 + tid];
    }

    float acc[4][4][4];
    #pragma unroll
    for (int mi = 0; mi < 4; mi++)
        #pragma unroll
        for (int ni = 0; ni < 4; ni++)
            #pragma unroll
            for (int e = 0; e < 4; e++) acc[mi][ni][e] = 0.f;

    const int rA = wm * 64 + (lane & 15);
    const int kAe = (lane >> 4) * 16;
    const int rB = wn * 32 + ((lane >> 4) & 1) * 8 + (lane & 7);
    const int kBe = ((lane >> 3) & 1) * 16;

    // per-unit constants (unit = tid + u*256; u=0..7)
    int uIsB[8], uBase[8];
    uint32_t uOff[8];
    const float* uPtr[8];
    #pragma unroll
    for (int u = 0; u < 8; u++) {
        int unit = tid + u * 256;
        int isB = unit >> 10;
        int loc = unit & 1023;
        int row = loc >> 3, ucol = loc & 7;
        uIsB[u] = isB;
        uBase[u] = isB ? B_HI : A_HI;
        uOff[u] = swz128((uint32_t)(row * 128 + ucol * 16));
        uPtr[u] = x + ((size_t)b * SS + (isB ? t0 : s0) + row) * HH + ucol * 8;
    }

    // ---- prologue: chunk 0 into buf 0 ----
    {
        char* stgp = smem + SM_STAGE;
        #pragma unroll
        for (int u = 0; u < 8; u++) {
            float4 v0 = *(const float4*)(uPtr[u]);
            float4 v1 = *(const float4*)(uPtr[u] + 4);
            cvt_store(stgp, uBase[u], uOff[u], v0, v1);
        }
    }
    __syncthreads();

    for (int i = 0; i < NCHUNK; i++) {
        const uint32_t stg = sb + SM_STAGE + (uint32_t)(i & 1) * STAGE_BYTES;
        char* stgn = smem + SM_STAGE + ((i + 1) & 1) * STAGE_BYTES;
        const bool more = (i + 1 < NCHUNK);
        const int kn = (i + 1) * KC;

        float4 p0[4], p1[4];
        // prefetch batch A (units 0-3) for next chunk
        if (more) {
            #pragma unroll
            for (int u = 0; u < 4; u++) {
                p0[u] = *(const float4*)(uPtr[u] + kn);
                p1[u] = *(const float4*)(uPtr[u] + kn + 4);
            }
        }
        // mma kk = 0,1
        #pragma unroll
        for (int kk = 0; kk < 2; kk++) {
            const uint32_t kb = kk * 32;
            uint32_t bh[2][4], bl[2][4];
            #pragma unroll
            for (int nb = 0; nb < 2; nb++) {
                uint32_t roff = (uint32_t)((rB + nb * 16) * 128 + kb + kBe);
                ldmx4(bh[nb], stg + B_HI + swz128(roff));
                ldmx4(bl[nb], stg + B_LO + swz128(roff));
            }
            uint32_t ah[4][4];
            #pragma unroll
            for (int mi = 0; mi < 4; mi++) {
                uint32_t roff = (uint32_t)((rA + mi * 16) * 128 + kb + kAe);
                ldmx4(ah[mi], stg + A_HI + swz128(roff));
            }
            #pragma unroll
            for (int mi = 0; mi < 4; mi++)
                #pragma unroll
                for (int ni = 0; ni < 4; ni++) {
                    mma16816(acc[mi][ni], ah[mi], &bh[ni >> 1][2 * (ni & 1)]);
                    mma16816(acc[mi][ni], ah[mi], &bl[ni >> 1][2 * (ni & 1)]);
                }
            uint32_t al[4][4];
            #pragma unroll
            for (int mi = 0; mi < 4; mi++) {
                uint32_t roff = (uint32_t)((rA + mi * 16) * 128 + kb + kAe);
                ldmx4(al[mi], stg + A_LO + swz128(roff));
            }
            #pragma unroll
            for (int mi = 0; mi < 4; mi++)
                #pragma unroll
                for (int ni = 0; ni < 4; ni++)
                    mma16816(acc[mi][ni], al[mi], &bh[ni >> 1][2 * (ni & 1)]);
        }
        // store batch A, prefetch batch B
        if (more) {
            #pragma unroll
            for (int u = 0; u < 4; u++)
                cvt_store(stgn, uBase[u], uOff[u], p0[u], p1[u]);
            #pragma unroll
            for (int u = 0; u < 4; u++) {
                p0[u] = *(const float4*)(uPtr[u + 4] + kn);
                p1[u] = *(const float4*)(uPtr[u + 4] + kn + 4);
            }
        }
        // mma kk = 2,3
        #pragma unroll
        for (int kk = 2; kk < 4; kk++) {
            const uint32_t kb = kk * 32;
            uint32_t bh[2][4], bl[2][4];
            #pragma unroll
            for (int nb = 0; nb < 2; nb++) {
                uint32_t roff = (uint32_t)((rB + nb * 16) * 128 + kb + kBe);
                ldmx4(bh[nb], stg + B_HI + swz128(roff));
                ldmx4(bl[nb], stg + B_LO + swz128(roff));
            }
            uint32_t ah[4][4];
            #pragma unroll
            for (int mi = 0; mi < 4; mi++) {
                uint32_t roff = (uint32_t)((rA + mi * 16) * 128 + kb + kAe);
                ldmx4(ah[mi], stg + A_HI + swz128(roff));
            }
            #pragma unroll
            for (int mi = 0; mi < 4; mi++)
                #pragma unroll
                for (int ni = 0; ni < 4; ni++) {
                    mma16816(acc[mi][ni], ah[mi], &bh[ni >> 1][2 * (ni & 1)]);
                    mma16816(acc[mi][ni], ah[mi], &bl[ni >> 1][2 * (ni & 1)]);
                }
            uint32_t al[4][4];
            #pragma unroll
            for (int mi = 0; mi < 4; mi++) {
                uint32_t roff = (uint32_t)((rA + mi * 16) * 128 + kb + kAe);
                ldmx4(al[mi], stg + A_LO + swz128(roff));
            }
            #pragma unroll
            for (int mi = 0; mi < 4; mi++)
                #pragma unroll
                for (int ni = 0; ni < 4; ni++)
                    mma16816(acc[mi][ni], al[mi], &bh[ni >> 1][2 * (ni & 1)]);
        }
        if (more) {
            #pragma unroll
            for (int u = 0; u < 4; u++)
                cvt_store(stgn, uBase[u + 4], uOff[u + 4], p0[u], p1[u]);
        }
        __syncthreads();
    }

    // ---- epilogue: W[s][t] = coef*band*G into smem ----
    float* Wb = (float*)(smem + SM_STAGE);
    #pragma unroll
    for (int mi = 0; mi < 4; mi++) {
        int r0 = wm * 64 + mi * 16 + (lane >> 2);
        int r1 = r0 + 8;
        float mq0 = mqS[r0], ma0 = maS[r0], mn0 = mnS[r0];
        float mq1 = mqS[r1], ma1 = maS[r1], mn1 = mnS[r1];
        int tn0 = turnS[r0], tn1 = turnS[r1];
        #pragma unroll
        for (int ni = 0; ni < 4; ni++) {
            int tb0 = wn * 32 + ni * 8 + (lane & 3) * 2;
            #pragma unroll
            for (int e = 0; e < 4; e++) {
                int srow = (e >> 1) ? r1 : r0;
                int tcol = tb0 + (e & 1);
                float mq_ = (e >> 1) ? mq1 : mq0;
                float ma_ = (e >> 1) ? ma1 : ma0;
                float mn_ = (e >> 1) ? mn1 : mn0;
                int tn_ = (e >> 1) ? tn1 : tn0;
                int dt = turnT[tcol] - tn_;
                float coef = fmaf(mq_, wqT[tcol], fmaf(ma_, waT[tcol], mn_ * wnT[tcol]));
                float v = (dt >= -VR && dt <= VR) ? coef * acc[mi][ni][e] : 0.f;
                Wb[srow * WSTRIDE + tcol] = v;
            }
        }
    }
    __syncthreads();
    if (tid < 128) {
        // t-side: alpha[t] += sum_s sW[s] * W[s,t]
        float aq = 0.f, aa = 0.f, an = 0.f;
        #pragma unroll 4
        for (int s = 0; s < 128; s++) {
            float wv = Wb[s * WSTRIDE + tid];
            aq = fmaf(sWq[s], wv, aq);
            aa = fmaf(sWa[s], wv, aa);
            an = fmaf(sWn[s], wv, an);
        }
        atomicAdd(&g_alpha[0][b * SS + t0 + tid], aq);
        atomicAdd(&g_alpha[1][b * SS + t0 + tid], aa);
        atomicAdd(&g_alpha[2][b * SS + t0 + tid], an);
        if (!diag) {
            // s-side mirror: alpha[s] += sum_t wT[t] * W[s,t]
            float bq = 0.f, ba = 0.f, bn = 0.f;
            #pragma unroll 4
            for (int t = 0; t < 128; t++) {
                float wv = Wb[tid * WSTRIDE + t];
                bq = fmaf(wqT[t], wv, bq);
                ba = fmaf(waT[t], wv, ba);
                bn = fmaf(wnT[t], wv, bn);
            }
            atomicAdd(&g_alpha[0][b * SS + s0 + tid], bq);
            atomicAdd(&g_alpha[1][b * SS + s0 + tid], ba);
            atomicAdd(&g_alpha[2][b * SS + s0 + tid], bn);
        }
    }
}

// ---------------------------------------------------------------------------
// Kernel 3: FUSED self + cross streaming pass, s-split with atomics.
// ---------------------------------------------------------------------------
__global__ void __launch_bounds__(256) k3_fused(const float* __restrict__ x) {
    const int b = blockIdx.y;
    const int h = blockIdx.x * 256 + threadIdx.x;
    const int sc = blockIdx.z;
    const int sbase = sc * SCHUNK;
    const int tid = threadIdx.x;

    __shared__ float smq[SCHUNK], sma[SCHUNK], smn[SCHUNK];
    __shared__ float scq[SCHUNK], sca[SCHUNK], scn[SCHUNK];
    for (int s = tid; s < SCHUNK; s += 256) {
        int gs = b * SS + sbase + s;
        float mq = g_mask[0][gs], ma = g_mask[1][gs], mn = g_mask[2][gs];
        smq[s] = mq; sma[s] = ma; smn[s] = mn;
        scq[s] = mq * g_alpha[0][gs];
        sca[s] = ma * g_alpha[1][gs];
        scn[s] = mn * g_alpha[2][gs];
    }
    __syncthreads();

    float m0 = g_msum[0][b], m1 = g_msum[1][b], m2 = g_msum[2][b];
    float rsq = 1.f / (m0 + AVG_EPS_);
    float rsa = 1.f / (m1 + AVG_EPS_);
    float rsn = 1.f / (m2 + AVG_EPS_);
    float rcq = 1.f / (m1 + m2 + AVG_EPS_);
    float rca = 1.f / (m0 + m2 + AVG_EPS_);
    float rcn = 1.f / (m0 + m1 + AVG_EPS_);

    const float* xb = x + ((size_t)b * SS + sbase) * HH + h;
    float aq = 0.f, aa = 0.f, an = 0.f;
    float bq = 0.f, ba = 0.f, bn = 0.f;
    #pragma unroll 4
    for (int s = 0; s < SCHUNK; s++) {
        float v = xb[(size_t)s * HH];
        aq = fmaf(smq[s], v, aq);
        aa = fmaf(sma[s], v, aa);
        an = fmaf(smn[s], v, an);
        bq = fmaf(scq[s], v, bq);
        ba = fmaf(sca[s], v, ba);
        bn = fmaf(scn[s], v, bn);
    }
    atomicAdd(&g_self[0][b * HH + h], aq * rsq);
    atomicAdd(&g_self[1][b * HH + h], aa * rsa);
    atomicAdd(&g_self[2][b * HH + h], an * rsn);
    atomicAdd(&g_cross[0][b * HH + h], bq * rcq);
    atomicAdd(&g_cross[1][b * HH + h], ba * rca);
    atomicAdd(&g_cross[2][b * HH + h], bn * rcn);
}

// ---------------------------------------------------------------------------
// Kernel 4: per-batch cosine logits; write q/a/n_output rows.
// ---------------------------------------------------------------------------
__global__ void k4_logits(float* __restrict__ out) {
    const int b = blockIdx.x;
    const int tid = threadIdx.x;
    float p[9];
    #pragma unroll
    for (int k = 0; k < 9; k++) p[k] = 0.f;
    for (int h = tid; h < HH; h += blockDim.x) {
        #pragma unroll
        for (int m = 0; m < 3; m++) {
            float sv = g_self[m][b * HH + h];
            float cv = g_cross[m][b * HH + h];
            p[m * 3 + 0] = fmaf(sv, cv, p[m * 3 + 0]);
            p[m * 3 + 1] = fmaf(sv, sv, p[m * 3 + 1]);
            p[m * 3 + 2] = fmaf(cv, cv, p[m * 3 + 2]);
        }
    }
    #pragma unroll
    for (int k = 0; k < 9; k++)
        #pragma unroll
        for (int o = 16; o > 0; o >>= 1)
            p[k] += __shfl_down_sync(0xffffffffu, p[k], o);
    __shared__ float red[9][8];
    if ((tid & 31) == 0) {
        int w = tid >> 5;
        #pragma unroll
        for (int k = 0; k < 9; k++) red[k][w] = p[k];
    }
    __syncthreads();
    if (tid == 0) {
        #pragma unroll
        for (int m = 0; m < 3; m++) {
            float dot = 0.f, n1 = 0.f, n2 = 0.f;
            for (int w = 0; w < 8; w++) {
                dot += red[m * 3 + 0][w];
                n1  += red[m * 3 + 1][w];
                n2  += red[m * 3 + 2][w];
            }
            float nx = fmaxf(sqrtf(n1), COS_EPS_);
            float ny = fmaxf(sqrtf(n2), COS_EPS_);
            float c = dot / (nx * ny);
            g_logits[m][b] = (c == 1.0f) ? __int_as_float(0x7fc00000) : c / TEMP_;
        }
    }
    if (b % SN == 0) {
        int g = b / SN;
        for (int h = tid; h < HH; h += blockDim.x) {
            out[1 + 0 * NG * HH + g * HH + h] = g_self[0][b * HH + h];
            out[1 + 1 * NG * HH + g * HH + h] = g_self[1][b * HH + h];
            out[1 + 2 * NG * HH + g * HH + h] = g_self[2][b * HH + h];
        }
    }
}

// ---------------------------------------------------------------------------
// Kernel 5: log-softmax + nanmean loss (tiny).
// ---------------------------------------------------------------------------
__global__ void k5_loss(const float* __restrict__ labels, float* __restrict__ out) {
    if (threadIdx.x != 0 || blockIdx.x != 0) return;
    float losses[3];
    for (int m = 0; m < 3; m++) {
        float sum = 0.f;
        int cnt = 0;
        for (int g = 0; g < NG; g++) {
            float l[SN];
            bool bad = false;
            for (int j = 0; j < SN; j++) {
                l[j] = g_logits[m][g * SN + j];
                if (isnan(l[j])) bad = true;
            }
            if (bad) continue;
            float mx = l[0];
            for (int j = 1; j < SN; j++) mx = fmaxf(mx, l[j]);
            float se = 0.f;
            for (int j = 0; j < SN; j++) se += expf(l[j] - mx);
            float lse = mx + logf(se);
            for (int j = 0; j < SN; j++) sum += (l[j] - lse) * labels[g * SN + j];
            cnt += SN;
        }
        losses[m] = -(sum / (float)cnt);
    }
    out[0] = (losses[1] + losses[0] + losses[2]) / 3.0f;
}

// ---------------------------------------------------------------------------
extern "C" void kernel_launch(void* const* d_in, const int* in_sizes, int n_in,
                              void* d_out, int out_size) {
    const float* x      = (const float*)d_in[0];
    const float* am     = (const float*)d_in[1];
    const float* labels = (const float*)d_in[2];
    const int*   qa     = (const int*)d_in[3];
    const int*   turn   = (const int*)d_in[4];
    float* out = (float*)d_out;

    cudaFuncSetAttribute(k2_mma, cudaFuncAttributeMaxDynamicSharedMemorySize, SMEM_BYTES);

    k0_masks<<<NB, 256>>>(am, qa);
    k2_mma<<<dim3(SS / TN, SS / TM, NB), 256, SMEM_BYTES>>>(x, turn);
    k3_fused<<<dim3(3, NB, SPLITS), 256>>>(x);
    k4_logits<<<NB, 256>>>(out);
    k5_loss<<<1, 32>>>(labels, out);
}

// round 9
// speedup vs baseline: 1.8956x; 1.0014x over previous
#include <cuda_runtime.h>
#include <math.h>
#include <cstdint>

namespace {
constexpr int NB = 72;
constexpr int SS = 512;
constexpr int HH = 768;
constexpr int NG = 8;
constexpr int SN = 9;
constexpr float TEMP_ = 0.07f;
constexpr float AVG_EPS_ = 1e-6f;
constexpr float COS_EPS_ = 1e-8f;
constexpr int VR = 2;
constexpr int SPLITS = 8;
constexpr int SCHUNK = SS / SPLITS;  // 64

// ---- gram tiling ----
constexpr int TM = 128, TN = 128, KC = 32;
constexpr int NCHUNK = HH / KC;  // 24

// ---- smem layout for gram kernel ----
constexpr int SM_TURNT = 0;      // int[128]
constexpr int SM_TURNS = 512;
constexpr int SM_WQT   = 1024;   // t-side w
constexpr int SM_WAT   = 1536;
constexpr int SM_WNT   = 2048;
constexpr int SM_MQS   = 2560;   // s-side raw masks
constexpr int SM_MAS   = 3072;
constexpr int SM_MNS   = 3584;
constexpr int SM_SWQ   = 4096;   // s-side w
constexpr int SM_SWA   = 4608;
constexpr int SM_SWN   = 5120;
constexpr int SM_STAGE = 6144;   // 2 x 32KB stage
constexpr int STAGE_BYTES = 32768;
constexpr int A_HI = 0, A_LO = 8192, B_HI = 16384, B_LO = 24576;
constexpr int WSTRIDE = 129;     // W overlay on stages (post-loop)
constexpr int SMEM_BYTES = SM_STAGE + 128 * WSTRIDE * 4;  // 72192 -> 2 CTAs/SM
}

// Scratch (no allocations allowed)
__device__ float g_mask[3][NB * SS];
__device__ float g_msum[3][NB];
__device__ float g_self[3][NB * HH];
__device__ float g_alpha[3][NB * SS];
__device__ float g_cross[3][NB * HH];
__device__ float g_logits[3][NB];

// ===================== helpers =====================
__device__ __forceinline__ uint32_t smem_u32(const void* p) {
    uint32_t a;
    asm("{ .reg .u64 t; cvta.to.shared.u64 t, %1; cvt.u32.u64 %0, t; }" : "=r"(a) : "l"(p));
    return a;
}
__device__ __forceinline__ uint32_t swz64(uint32_t off) { return off ^ ((off >> 3) & 0x30); }

__device__ __forceinline__ void ldmx4(uint32_t* r, uint32_t addr) {
    asm volatile("ldmatrix.sync.aligned.m8n8.x4.shared.b16 {%0,%1,%2,%3}, [%4];"
                 : "=r"(r[0]), "=r"(r[1]), "=r"(r[2]), "=r"(r[3]) : "r"(addr));
}
__device__ __forceinline__ void mma16816(float* d, const uint32_t* a, const uint32_t* b) {
    asm volatile(
        "mma.sync.aligned.m16n8k16.row.col.f32.bf16.bf16.f32 "
        "{%0,%1,%2,%3}, {%4,%5,%6,%7}, {%8,%9}, {%0,%1,%2,%3};"
        : "+f"(d[0]), "+f"(d[1]), "+f"(d[2]), "+f"(d[3])
        : "r"(a[0]), "r"(a[1]), "r"(a[2]), "r"(a[3]), "r"(b[0]), "r"(b[1]));
}

// convert 2 float4 -> hi/lo bf16x8 and store swizzled (LO plane at +8KB)
__device__ __forceinline__ void cvt_store(char* stgp, int base, uint32_t off,
                                          const float4& v0, const float4& v1) {
    uint32_t i0 = __float_as_uint(v0.x), i1 = __float_as_uint(v0.y);
    uint32_t i2 = __float_as_uint(v0.z), i3 = __float_as_uint(v0.w);
    uint32_t i4 = __float_as_uint(v1.x), i5 = __float_as_uint(v1.y);
    uint32_t i6 = __float_as_uint(v1.z), i7 = __float_as_uint(v1.w);
    uint4 Hi;
    Hi.x = __byte_perm(i0, i1, 0x7632);
    Hi.y = __byte_perm(i2, i3, 0x7632);
    Hi.z = __byte_perm(i4, i5, 0x7632);
    Hi.w = __byte_perm(i6, i7, 0x7632);
    uint32_t l0 = __float_as_uint(v0.x - __uint_as_float(i0 & 0xffff0000u));
    uint32_t l1 = __float_as_uint(v0.y - __uint_as_float(i1 & 0xffff0000u));
    uint32_t l2 = __float_as_uint(v0.z - __uint_as_float(i2 & 0xffff0000u));
    uint32_t l3 = __float_as_uint(v0.w - __uint_as_float(i3 & 0xffff0000u));
    uint32_t l4 = __float_as_uint(v1.x - __uint_as_float(i4 & 0xffff0000u));
    uint32_t l5 = __float_as_uint(v1.y - __uint_as_float(i5 & 0xffff0000u));
    uint32_t l6 = __float_as_uint(v1.z - __uint_as_float(i6 & 0xffff0000u));
    uint32_t l7 = __float_as_uint(v1.w - __uint_as_float(i7 & 0xffff0000u));
    uint4 Lo;
    Lo.x = __byte_perm(l0, l1, 0x7632);
    Lo.y = __byte_perm(l2, l3, 0x7632);
    Lo.z = __byte_perm(l4, l5, 0x7632);
    Lo.w = __byte_perm(l6, l7, 0x7632);
    *(uint4*)(stgp + base + off) = Hi;
    *(uint4*)(stgp + base + 8192 + off) = Lo;
}

// ---------------------------------------------------------------------------
// Kernel 0: grid (NB, 2). part 0: masks + sums + zero alpha. part 1: zero h-bufs.
// ---------------------------------------------------------------------------
__global__ void k0_masks(const float* __restrict__ am,
                         const int* __restrict__ qa) {
    const int b = blockIdx.x;
    const int tid = threadIdx.x;
    if (blockIdx.y == 1) {
        for (int h = tid; h < HH; h += blockDim.x) {
            #pragma unroll
            for (int m = 0; m < 3; m++) {
                g_self[m][b * HH + h] = 0.f;
                g_cross[m][b * HH + h] = 0.f;
            }
        }
        return;
    }
    __shared__ float red[3][8];
    float pq = 0.f, pa = 0.f, pn = 0.f;
    for (int s = tid; s < SS; s += blockDim.x) {
        int q = qa[b * SS + s];
        float a = am[b * SS + s];
        float mq = (q == 1 || q == 2) ? a : 0.f;
        float ma = (q == 0 || q == 2) ? a : 0.f;
        float mn = (q == 3) ? a : 0.f;
        g_mask[0][b * SS + s] = mq;
        g_mask[1][b * SS + s] = ma;
        g_mask[2][b * SS + s] = mn;
        g_alpha[0][b * SS + s] = 0.f;
        g_alpha[1][b * SS + s] = 0.f;
        g_alpha[2][b * SS + s] = 0.f;
        pq += mq; pa += ma; pn += mn;
    }
    #pragma unroll
    for (int o = 16; o > 0; o >>= 1) {
        pq += __shfl_down_sync(0xffffffffu, pq, o);
        pa += __shfl_down_sync(0xffffffffu, pa, o);
        pn += __shfl_down_sync(0xffffffffu, pn, o);
    }
    if ((tid & 31) == 0) {
        int w = tid >> 5;
        red[0][w] = pq; red[1][w] = pa; red[2][w] = pn;
    }
    __syncthreads();
    if (tid == 0) {
        int nw = blockDim.x >> 5;
        float s0 = 0.f, s1 = 0.f, s2 = 0.f;
        for (int w = 0; w < nw; w++) { s0 += red[0][w]; s1 += red[1][w]; s2 += red[2][w]; }
        g_msum[0][b] = s0; g_msum[1][b] = s1; g_msum[2][b] = s2;
    }
}

// ---------------------------------------------------------------------------
// Kernel 2: banded SYMMETRIC Gram via mma.sync bf16 hi/lo (3 passes).
// KC=32, SW64 stage, 2 CTAs/SM. Upper triangle; dual gemv epilogue mirrors.
// ---------------------------------------------------------------------------
__global__ void __launch_bounds__(256, 2)
k2_mma(const float* __restrict__ x, const int* __restrict__ turn) {
    const int b = blockIdx.z;
    const int I = blockIdx.y, J = blockIdx.x;
    if (J < I) return;
    const int s0 = I * TM, t0 = J * TN;
    const int* tb = turn + b * SS;
    if (tb[t0] - tb[s0 + TM - 1] > VR) return;
    const bool diag = (I == J);

    extern __shared__ char smem[];
    const uint32_t sb = smem_u32(smem);
    const int tid = threadIdx.x, wid = tid >> 5, lane = tid & 31;
    const int wm = wid & 1, wn = wid >> 1;

    int*   turnT = (int*)(smem + SM_TURNT);
    int*   turnS = (int*)(smem + SM_TURNS);
    float* wqT = (float*)(smem + SM_WQT);
    float* waT = (float*)(smem + SM_WAT);
    float* wnT = (float*)(smem + SM_WNT);
    float* mqS = (float*)(smem + SM_MQS);
    float* maS = (float*)(smem + SM_MAS);
    float* mnS = (float*)(smem + SM_MNS);
    float* sWq = (float*)(smem + SM_SWQ);
    float* sWa = (float*)(smem + SM_SWA);
    float* sWn = (float*)(smem + SM_SWN);
    if (tid < 128) {
        int gt = b * SS + t0 + tid;
        float mq = g_mask[0][gt], ma = g_mask[1][gt], mn = g_mask[2][gt];
        wqT[tid] = ma + mn; waT[tid] = mq + mn; wnT[tid] = mq + ma;
        turnT[tid] = tb[t0 + tid];
        int gs = b * SS + s0 + tid;
        float mqs = g_mask[0][gs], mas = g_mask[1][gs], mns = g_mask[2][gs];
        mqS[tid] = mqs; maS[tid] = mas; mnS[tid] = mns;
        sWq[tid] = mas + mns; sWa[tid] = mqs + mns; sWn[tid] = mqs + mas;
        turnS[tid] = tb[s0 + tid];
    }

    float acc[4][4][4];
    #pragma unroll
    for (int mi = 0; mi < 4; mi++)
        #pragma unroll
        for (int ni = 0; ni < 4; ni++)
            #pragma unroll
            for (int e = 0; e < 4; e++) acc[mi][ni][e] = 0.f;

    const int rA = wm * 64 + (lane & 15);
    const int kAe = (lane >> 4) * 16;
    const int rB = wn * 32 + ((lane >> 4) & 1) * 8 + (lane & 7);
    const int kBe = ((lane >> 3) & 1) * 16;

    // per-unit constants (unit = tid + u*256; u=0..3). KC=32 -> 1024 units/chunk.
    int uBase[4];
    uint32_t uOff[4];
    const float* uPtr[4];
    #pragma unroll
    for (int u = 0; u < 4; u++) {
        int unit = tid + u * 256;
        int isB = unit >> 9;
        int loc = unit & 511;
        int row = loc >> 2, ucol = loc & 3;
        uBase[u] = isB ? B_HI : A_HI;
        uOff[u] = swz64((uint32_t)(row * 64 + ucol * 16));
        uPtr[u] = x + ((size_t)b * SS + (isB ? t0 : s0) + row) * HH + ucol * 8;
    }

    // ---- prologue: chunk 0 into buf 0 ----
    {
        char* stgp = smem + SM_STAGE;
        #pragma unroll
        for (int u = 0; u < 4; u++) {
            float4 v0 = *(const float4*)(uPtr[u]);
            float4 v1 = *(const float4*)(uPtr[u] + 4);
            cvt_store(stgp, uBase[u], uOff[u], v0, v1);
        }
    }
    __syncthreads();

    for (int i = 0; i < NCHUNK; i++) {
        const uint32_t stg = sb + SM_STAGE + (uint32_t)(i & 1) * STAGE_BYTES;
        char* stgn = smem + SM_STAGE + ((i + 1) & 1) * STAGE_BYTES;
        const bool more = (i + 1 < NCHUNK);
        const int kn = (i + 1) * KC;

        float4 p0[2], p1[2];
        if (more) {
            #pragma unroll
            for (int u = 0; u < 2; u++) {
                p0[u] = *(const float4*)(uPtr[u] + kn);
                p1[u] = *(const float4*)(uPtr[u] + kn + 4);
            }
        }
        // ---- kk = 0 ----
        {
            const uint32_t kb = 0;
            uint32_t bh[2][4], bl[2][4];
            #pragma unroll
            for (int nb = 0; nb < 2; nb++) {
                uint32_t roff = (uint32_t)((rB + nb * 16) * 64 + kb + kBe);
                ldmx4(bh[nb], stg + B_HI + swz64(roff));
                ldmx4(bl[nb], stg + B_LO + swz64(roff));
            }
            uint32_t ah[4][4];
            #pragma unroll
            for (int mi = 0; mi < 4; mi++) {
                uint32_t roff = (uint32_t)((rA + mi * 16) * 64 + kb + kAe);
                ldmx4(ah[mi], stg + A_HI + swz64(roff));
            }
            #pragma unroll
            for (int mi = 0; mi < 4; mi++)
                #pragma unroll
                for (int ni = 0; ni < 4; ni++) {
                    mma16816(acc[mi][ni], ah[mi], &bh[ni >> 1][2 * (ni & 1)]);
                    mma16816(acc[mi][ni], ah[mi], &bl[ni >> 1][2 * (ni & 1)]);
                }
            uint32_t al[4][4];
            #pragma unroll
            for (int mi = 0; mi < 4; mi++) {
                uint32_t roff = (uint32_t)((rA + mi * 16) * 64 + kb + kAe);
                ldmx4(al[mi], stg + A_LO + swz64(roff));
            }
            #pragma unroll
            for (int mi = 0; mi < 4; mi++)
                #pragma unroll
                for (int ni = 0; ni < 4; ni++)
                    mma16816(acc[mi][ni], al[mi], &bh[ni >> 1][2 * (ni & 1)]);
        }
        if (more) {
            #pragma unroll
            for (int u = 0; u < 2; u++)
                cvt_store(stgn, uBase[u], uOff[u], p0[u], p1[u]);
            #pragma unroll
            for (int u = 0; u < 2; u++) {
                p0[u] = *(const float4*)(uPtr[u + 2] + kn);
                p1[u] = *(const float4*)(uPtr[u + 2] + kn + 4);
            }
        }
        // ---- kk = 1 ----
        {
            const uint32_t kb = 32;
            uint32_t bh[2][4], bl[2][4];
            #pragma unroll
            for (int nb = 0; nb < 2; nb++) {
                uint32_t roff = (uint32_t)((rB + nb * 16) * 64 + kb + kBe);
                ldmx4(bh[nb], stg + B_HI + swz64(roff));
                ldmx4(bl[nb], stg + B_LO + swz64(roff));
            }
            uint32_t ah[4][4];
            #pragma unroll
            for (int mi = 0; mi < 4; mi++) {
                uint32_t roff = (uint32_t)((rA + mi * 16) * 64 + kb + kAe);
                ldmx4(ah[mi], stg + A_HI + swz64(roff));
            }
            #pragma unroll
            for (int mi = 0; mi < 4; mi++)
                #pragma unroll
                for (int ni = 0; ni < 4; ni++) {
                    mma16816(acc[mi][ni], ah[mi], &bh[ni >> 1][2 * (ni & 1)]);
                    mma16816(acc[mi][ni], ah[mi], &bl[ni >> 1][2 * (ni & 1)]);
                }
            uint32_t al[4][4];
            #pragma unroll
            for (int mi = 0; mi < 4; mi++) {
                uint32_t roff = (uint32_t)((rA + mi * 16) * 64 + kb + kAe);
                ldmx4(al[mi], stg + A_LO + swz64(roff));
            }
            #pragma unroll
            for (int mi = 0; mi < 4; mi++)
                #pragma unroll
                for (int ni = 0; ni < 4; ni++)
                    mma16816(acc[mi][ni], al[mi], &bh[ni >> 1][2 * (ni & 1)]);
        }
        if (more) {
            #pragma unroll
            for (int u = 0; u < 2; u++)
                cvt_store(stgn, uBase[u + 2], uOff[u + 2], p0[u], p1[u]);
        }
        __syncthreads();
    }

    // ---- epilogue: W[s][t] = coef*band*G into smem (overlay on stages) ----
    float* Wb = (float*)(smem + SM_STAGE);
    #pragma unroll
    for (int mi = 0; mi < 4; mi++) {
        int r0 = wm * 64 + mi * 16 + (lane >> 2);
        int r1 = r0 + 8;
        float mq0 = mqS[r0], ma0 = maS[r0], mn0 = mnS[r0];
        float mq1 = mqS[r1], ma1 = maS[r1], mn1 = mnS[r1];
        int tn0 = turnS[r0], tn1 = turnS[r1];
        #pragma unroll
        for (int ni = 0; ni < 4; ni++) {
            int tb0 = wn * 32 + ni * 8 + (lane & 3) * 2;
            #pragma unroll
            for (int e = 0; e < 4; e++) {
                int srow = (e >> 1) ? r1 : r0;
                int tcol = tb0 + (e & 1);
                float mq_ = (e >> 1) ? mq1 : mq0;
                float ma_ = (e >> 1) ? ma1 : ma0;
                float mn_ = (e >> 1) ? mn1 : mn0;
                int tn_ = (e >> 1) ? tn1 : tn0;
                int dt = turnT[tcol] - tn_;
                float coef = fmaf(mq_, wqT[tcol], fmaf(ma_, waT[tcol], mn_ * wnT[tcol]));
                float v = (dt >= -VR && dt <= VR) ? coef * acc[mi][ni][e] : 0.f;
                Wb[srow * WSTRIDE + tcol] = v;
            }
        }
    }
    __syncthreads();
    if (tid < 128) {
        float aq = 0.f, aa = 0.f, an = 0.f;
        #pragma unroll 4
        for (int s = 0; s < 128; s++) {
            float wv = Wb[s * WSTRIDE + tid];
            aq = fmaf(sWq[s], wv, aq);
            aa = fmaf(sWa[s], wv, aa);
            an = fmaf(sWn[s], wv, an);
        }
        atomicAdd(&g_alpha[0][b * SS + t0 + tid], aq);
        atomicAdd(&g_alpha[1][b * SS + t0 + tid], aa);
        atomicAdd(&g_alpha[2][b * SS + t0 + tid], an);
        if (!diag) {
            float bq = 0.f, ba = 0.f, bn = 0.f;
            #pragma unroll 4
            for (int t = 0; t < 128; t++) {
                float wv = Wb[tid * WSTRIDE + t];
                bq = fmaf(wqT[t], wv, bq);
                ba = fmaf(waT[t], wv, ba);
                bn = fmaf(wnT[t], wv, bn);
            }
            atomicAdd(&g_alpha[0][b * SS + s0 + tid], bq);
            atomicAdd(&g_alpha[1][b * SS + s0 + tid], ba);
            atomicAdd(&g_alpha[2][b * SS + s0 + tid], bn);
        }
    }
}

// ---------------------------------------------------------------------------
// Kernel 3: FUSED self + cross streaming pass, s-split with atomics.
// ---------------------------------------------------------------------------
__global__ void __launch_bounds__(256) k3_fused(const float* __restrict__ x) {
    const int b = blockIdx.y;
    const int h = blockIdx.x * 256 + threadIdx.x;
    const int sc = blockIdx.z;
    const int sbase = sc * SCHUNK;
    const int tid = threadIdx.x;

    __shared__ float smq[SCHUNK], sma[SCHUNK], smn[SCHUNK];
    __shared__ float scq[SCHUNK], sca[SCHUNK], scn[SCHUNK];
    for (int s = tid; s < SCHUNK; s += 256) {
        int gs = b * SS + sbase + s;
        float mq = g_mask[0][gs], ma = g_mask[1][gs], mn = g_mask[2][gs];
        smq[s] = mq; sma[s] = ma; smn[s] = mn;
        scq[s] = mq * g_alpha[0][gs];
        sca[s] = ma * g_alpha[1][gs];
        scn[s] = mn * g_alpha[2][gs];
    }
    __syncthreads();

    float m0 = g_msum[0][b], m1 = g_msum[1][b], m2 = g_msum[2][b];
    float rsq = 1.f / (m0 + AVG_EPS_);
    float rsa = 1.f / (m1 + AVG_EPS_);
    float rsn = 1.f / (m2 + AVG_EPS_);
    float rcq = 1.f / (m1 + m2 + AVG_EPS_);
    float rca = 1.f / (m0 + m2 + AVG_EPS_);
    float rcn = 1.f / (m0 + m1 + AVG_EPS_);

    const float* xb = x + ((size_t)b * SS + sbase) * HH + h;
    float aq = 0.f, aa = 0.f, an = 0.f;
    float bq = 0.f, ba = 0.f, bn = 0.f;
    #pragma unroll 4
    for (int s = 0; s < SCHUNK; s++) {
        float v = xb[(size_t)s * HH];
        aq = fmaf(smq[s], v, aq);
        aa = fmaf(sma[s], v, aa);
        an = fmaf(smn[s], v, an);
        bq = fmaf(scq[s], v, bq);
        ba = fmaf(sca[s], v, ba);
        bn = fmaf(scn[s], v, bn);
    }
    atomicAdd(&g_self[0][b * HH + h], aq * rsq);
    atomicAdd(&g_self[1][b * HH + h], aa * rsa);
    atomicAdd(&g_self[2][b * HH + h], an * rsn);
    atomicAdd(&g_cross[0][b * HH + h], bq * rcq);
    atomicAdd(&g_cross[1][b * HH + h], ba * rca);
    atomicAdd(&g_cross[2][b * HH + h], bn * rcn);
}

// ---------------------------------------------------------------------------
// Kernel 4: per-batch cosine logits; write q/a/n_output rows.
// ---------------------------------------------------------------------------
__global__ void k4_logits(float* __restrict__ out) {
    const int b = blockIdx.x;
    const int tid = threadIdx.x;
    float p[9];
    #pragma unroll
    for (int k = 0; k < 9; k++) p[k] = 0.f;
    for (int h = tid; h < HH; h += blockDim.x) {
        #pragma unroll
        for (int m = 0; m < 3; m++) {
            float sv = g_self[m][b * HH + h];
            float cv = g_cross[m][b * HH + h];
            p[m * 3 + 0] = fmaf(sv, cv, p[m * 3 + 0]);
            p[m * 3 + 1] = fmaf(sv, sv, p[m * 3 + 1]);
            p[m * 3 + 2] = fmaf(cv, cv, p[m * 3 + 2]);
        }
    }
    #pragma unroll
    for (int k = 0; k < 9; k++)
        #pragma unroll
        for (int o = 16; o > 0; o >>= 1)
            p[k] += __shfl_down_sync(0xffffffffu, p[k], o);
    __shared__ float red[9][8];
    if ((tid & 31) == 0) {
        int w = tid >> 5;
        #pragma unroll
        for (int k = 0; k < 9; k++) red[k][w] = p[k];
    }
    __syncthreads();
    if (tid == 0) {
        #pragma unroll
        for (int m = 0; m < 3; m++) {
            float dot = 0.f, n1 = 0.f, n2 = 0.f;
            for (int w = 0; w < 8; w++) {
                dot += red[m * 3 + 0][w];
                n1  += red[m * 3 + 1][w];
                n2  += red[m * 3 + 2][w];
            }
            float nx = fmaxf(sqrtf(n1), COS_EPS_);
            float ny = fmaxf(sqrtf(n2), COS_EPS_);
            float c = dot / (nx * ny);
            g_logits[m][b] = (c == 1.0f) ? __int_as_float(0x7fc00000) : c / TEMP_;
        }
    }
    if (b % SN == 0) {
        int g = b / SN;
        for (int h = tid; h < HH; h += blockDim.x) {
            out[1 + 0 * NG * HH + g * HH + h] = g_self[0][b * HH + h];
            out[1 + 1 * NG * HH + g * HH + h] = g_self[1][b * HH + h];
            out[1 + 2 * NG * HH + g * HH + h] = g_self[2][b * HH + h];
        }
    }
}

// ---------------------------------------------------------------------------
// Kernel 5: log-softmax + nanmean loss (tiny).
// ---------------------------------------------------------------------------
__global__ void k5_loss(const float* __restrict__ labels, float* __restrict__ out) {
    if (threadIdx.x != 0 || blockIdx.x != 0) return;
    float losses[3];
    for (int m = 0; m < 3; m++) {
        float sum = 0.f;
        int cnt = 0;
        for (int g = 0; g < NG; g++) {
            float l[SN];
            bool bad = false;
            for (int j = 0; j < SN; j++) {
                l[j] = g_logits[m][g * SN + j];
                if (isnan(l[j])) bad = true;
            }
            if (bad) continue;
            float mx = l[0];
            for (int j = 1; j < SN; j++) mx = fmaxf(mx, l[j]);
            float se = 0.f;
            for (int j = 0; j < SN; j++) se += expf(l[j] - mx);
            float lse = mx + logf(se);
            for (int j = 0; j < SN; j++) sum += (l[j] - lse) * labels[g * SN + j];
            cnt += SN;
        }
        losses[m] = -(sum / (float)cnt);
    }
    out[0] = (losses[1] + losses[0] + losses[2]) / 3.0f;
}

// ---------------------------------------------------------------------------
extern "C" void kernel_launch(void* const* d_in, const int* in_sizes, int n_in,
                              void* d_out, int out_size) {
    const float* x      = (const float*)d_in[0];
    const float* am     = (const float*)d_in[1];
    const float* labels = (const float*)d_in[2];
    const int*   qa     = (const int*)d_in[3];
    const int*   turn   = (const int*)d_in[4];
    float* out = (float*)d_out;

    cudaFuncSetAttribute(k2_mma, cudaFuncAttributeMaxDynamicSharedMemorySize, SMEM_BYTES);

    k0_masks<<<dim3(NB, 2), 256>>>(am, qa);
    k2_mma<<<dim3(SS / TN, SS / TM, NB), 256, SMEM_BYTES>>>(x, turn);
    k3_fused<<<dim3(3, NB, SPLITS), 256>>>(x);
    k4_logits<<<NB, 256>>>(out);
    k5_loss<<<1, 32>>>(labels, out);
}

// round 10
// speedup vs baseline: 2.3539x; 1.2418x over previous
#include <cuda_runtime.h>
#include <cuda_fp16.h>
#include <math.h>
#include <cstdint>

namespace {
constexpr int NB = 72;
constexpr int SS = 512;
constexpr int HH = 768;
constexpr int NG = 8;
constexpr int SN = 9;
constexpr float TEMP_ = 0.07f;
constexpr float AVG_EPS_ = 1e-6f;
constexpr float COS_EPS_ = 1e-8f;
constexpr int VR = 2;
constexpr int SPLITS = 8;
constexpr int SCHUNK = SS / SPLITS;  // 64

// ---- gram tiling ----
constexpr int TM = 128, TN = 128, KC = 32;
constexpr int NCHUNK = HH / KC;  // 24

// ---- smem layout for gram kernel ----
constexpr int SM_TURNT = 0;      // int[128]
constexpr int SM_TURNS = 512;
constexpr int SM_WQT   = 1024;   // t-side w
constexpr int SM_WAT   = 1536;
constexpr int SM_WNT   = 2048;
constexpr int SM_MQS   = 2560;   // s-side raw masks
constexpr int SM_MAS   = 3072;
constexpr int SM_MNS   = 3584;
constexpr int SM_SWQ   = 4096;   // s-side w
constexpr int SM_SWA   = 4608;
constexpr int SM_SWN   = 5120;
constexpr int SM_STAGE = 6144;   // 2 x 24KB stage (A_HI, B_HI, B_LO)
constexpr int STAGE_BYTES = 24576;
constexpr int A_HI = 0, B_HI = 8192, B_LO = 16384;
constexpr int WSTRIDE = 129;     // W overlay on stages (post-loop), 66048 B
constexpr int SMEM_BYTES = SM_STAGE + 128 * WSTRIDE * 4;  // 72192 -> 2 CTAs/SM
}

// Scratch (no allocations allowed)
__device__ float g_mask[3][NB * SS];
__device__ float g_msum[3][NB];
__device__ float g_self[3][NB * HH];
__device__ float g_alpha[3][NB * SS];
__device__ float g_cross[3][NB * HH];
__device__ float g_logits[3][NB];

// ===================== helpers =====================
__device__ __forceinline__ uint32_t smem_u32(const void* p) {
    uint32_t a;
    asm("{ .reg .u64 t; cvta.to.shared.u64 t, %1; cvt.u32.u64 %0, t; }" : "=r"(a) : "l"(p));
    return a;
}
__device__ __forceinline__ uint32_t swz64(uint32_t off) { return off ^ ((off >> 3) & 0x30); }

__device__ __forceinline__ void ldmx4(uint32_t* r, uint32_t addr) {
    asm volatile("ldmatrix.sync.aligned.m8n8.x4.shared.b16 {%0,%1,%2,%3}, [%4];"
                 : "=r"(r[0]), "=r"(r[1]), "=r"(r[2]), "=r"(r[3]) : "r"(addr));
}
__device__ __forceinline__ void mma16816(float* d, const uint32_t* a, const uint32_t* b) {
    asm volatile(
        "mma.sync.aligned.m16n8k16.row.col.f32.f16.f16.f32 "
        "{%0,%1,%2,%3}, {%4,%5,%6,%7}, {%8,%9}, {%0,%1,%2,%3};"
        : "+f"(d[0]), "+f"(d[1]), "+f"(d[2]), "+f"(d[3])
        : "r"(a[0]), "r"(a[1]), "r"(a[2]), "r"(a[3]), "r"(b[0]), "r"(b[1]));
}

__device__ __forceinline__ uint32_t h2u(__half2 h) {
    return *reinterpret_cast<uint32_t*>(&h);
}

// fp32x8 -> fp16 hi plane only (A side)
__device__ __forceinline__ void cvt_store_hi(char* stgp, uint32_t off,
                                             const float4& v0, const float4& v1) {
    uint4 Hi;
    Hi.x = h2u(__floats2half2_rn(v0.x, v0.y));
    Hi.y = h2u(__floats2half2_rn(v0.z, v0.w));
    Hi.z = h2u(__floats2half2_rn(v1.x, v1.y));
    Hi.w = h2u(__floats2half2_rn(v1.z, v1.w));
    *(uint4*)(stgp + A_HI + off) = Hi;
}

// fp32x8 -> fp16 hi + lo planes (B side; LO at B_LO)
__device__ __forceinline__ void cvt_store_hilo(char* stgp, uint32_t off,
                                               const float4& v0, const float4& v1) {
    __half2 h0 = __floats2half2_rn(v0.x, v0.y);
    __half2 h1 = __floats2half2_rn(v0.z, v0.w);
    __half2 h2_ = __floats2half2_rn(v1.x, v1.y);
    __half2 h3 = __floats2half2_rn(v1.z, v1.w);
    uint4 Hi;
    Hi.x = h2u(h0); Hi.y = h2u(h1); Hi.z = h2u(h2_); Hi.w = h2u(h3);
    float2 f0 = __half22float2(h0);
    float2 f1 = __half22float2(h1);
    float2 f2 = __half22float2(h2_);
    float2 f3 = __half22float2(h3);
    uint4 Lo;
    Lo.x = h2u(__floats2half2_rn(v0.x - f0.x, v0.y - f0.y));
    Lo.y = h2u(__floats2half2_rn(v0.z - f1.x, v0.w - f1.y));
    Lo.z = h2u(__floats2half2_rn(v1.x - f2.x, v1.y - f2.y));
    Lo.w = h2u(__floats2half2_rn(v1.z - f3.x, v1.w - f3.y));
    *(uint4*)(stgp + B_HI + off) = Hi;
    *(uint4*)(stgp + B_LO + off) = Lo;
}

// ---------------------------------------------------------------------------
// Kernel 0: grid (NB, 2). part 0: masks + sums + zero alpha. part 1: zero h-bufs.
// ---------------------------------------------------------------------------
__global__ void k0_masks(const float* __restrict__ am,
                         const int* __restrict__ qa) {
    const int b = blockIdx.x;
    const int tid = threadIdx.x;
    if (blockIdx.y == 1) {
        for (int h = tid; h < HH; h += blockDim.x) {
            #pragma unroll
            for (int m = 0; m < 3; m++) {
                g_self[m][b * HH + h] = 0.f;
                g_cross[m][b * HH + h] = 0.f;
            }
        }
        return;
    }
    __shared__ float red[3][8];
    float pq = 0.f, pa = 0.f, pn = 0.f;
    for (int s = tid; s < SS; s += blockDim.x) {
        int q = qa[b * SS + s];
        float a = am[b * SS + s];
        float mq = (q == 1 || q == 2) ? a : 0.f;
        float ma = (q == 0 || q == 2) ? a : 0.f;
        float mn = (q == 3) ? a : 0.f;
        g_mask[0][b * SS + s] = mq;
        g_mask[1][b * SS + s] = ma;
        g_mask[2][b * SS + s] = mn;
        g_alpha[0][b * SS + s] = 0.f;
        g_alpha[1][b * SS + s] = 0.f;
        g_alpha[2][b * SS + s] = 0.f;
        pq += mq; pa += ma; pn += mn;
    }
    #pragma unroll
    for (int o = 16; o > 0; o >>= 1) {
        pq += __shfl_down_sync(0xffffffffu, pq, o);
        pa += __shfl_down_sync(0xffffffffu, pa, o);
        pn += __shfl_down_sync(0xffffffffu, pn, o);
    }
    if ((tid & 31) == 0) {
        int w = tid >> 5;
        red[0][w] = pq; red[1][w] = pa; red[2][w] = pn;
    }
    __syncthreads();
    if (tid == 0) {
        int nw = blockDim.x >> 5;
        float s0 = 0.f, s1 = 0.f, s2 = 0.f;
        for (int w = 0; w < nw; w++) { s0 += red[0][w]; s1 += red[1][w]; s2 += red[2][w]; }
        g_msum[0][b] = s0; g_msum[1][b] = s1; g_msum[2][b] = s2;
    }
}

// ---------------------------------------------------------------------------
// Kernel 2: banded SYMMETRIC Gram via mma.sync fp16 hi/lo, 2 passes:
//   G = A_hi * B_hi + A_hi * B_lo   (error = A_lo*B ~ 2^-11, well under tol)
// KC=32, SW64 stage. Upper triangle; dual gemv epilogue mirrors.
// ---------------------------------------------------------------------------
__global__ void __launch_bounds__(256, 2)
k2_mma(const float* __restrict__ x, const int* __restrict__ turn) {
    const int b = blockIdx.z;
    const int I = blockIdx.y, J = blockIdx.x;
    if (J < I) return;
    const int s0 = I * TM, t0 = J * TN;
    const int* tb = turn + b * SS;
    if (tb[t0] - tb[s0 + TM - 1] > VR) return;
    const bool diag = (I == J);

    extern __shared__ char smem[];
    const uint32_t sb = smem_u32(smem);
    const int tid = threadIdx.x, wid = tid >> 5, lane = tid & 31;
    const int wm = wid & 1, wn = wid >> 1;

    int*   turnT = (int*)(smem + SM_TURNT);
    int*   turnS = (int*)(smem + SM_TURNS);
    float* wqT = (float*)(smem + SM_WQT);
    float* waT = (float*)(smem + SM_WAT);
    float* wnT = (float*)(smem + SM_WNT);
    float* mqS = (float*)(smem + SM_MQS);
    float* maS = (float*)(smem + SM_MAS);
    float* mnS = (float*)(smem + SM_MNS);
    float* sWq = (float*)(smem + SM_SWQ);
    float* sWa = (float*)(smem + SM_SWA);
    float* sWn = (float*)(smem + SM_SWN);
    if (tid < 128) {
        int gt = b * SS + t0 + tid;
        float mq = g_mask[0][gt], ma = g_mask[1][gt], mn = g_mask[2][gt];
        wqT[tid] = ma + mn; waT[tid] = mq + mn; wnT[tid] = mq + ma;
        turnT[tid] = tb[t0 + tid];
        int gs = b * SS + s0 + tid;
        float mqs = g_mask[0][gs], mas = g_mask[1][gs], mns = g_mask[2][gs];
        mqS[tid] = mqs; maS[tid] = mas; mnS[tid] = mns;
        sWq[tid] = mas + mns; sWa[tid] = mqs + mns; sWn[tid] = mqs + mas;
        turnS[tid] = tb[s0 + tid];
    }

    float acc[4][4][4];
    #pragma unroll
    for (int mi = 0; mi < 4; mi++)
        #pragma unroll
        for (int ni = 0; ni < 4; ni++)
            #pragma unroll
            for (int e = 0; e < 4; e++) acc[mi][ni][e] = 0.f;

    const int rA = wm * 64 + (lane & 15);
    const int kAe = (lane >> 4) * 16;
    const int rB = wn * 32 + ((lane >> 4) & 1) * 8 + (lane & 7);
    const int kBe = ((lane >> 3) & 1) * 16;

    // per-unit constants (unit = tid + u*256; u=0..3). u<2 -> A tile, u>=2 -> B tile.
    uint32_t uOff[4];
    const float* uPtr[4];
    #pragma unroll
    for (int u = 0; u < 4; u++) {
        int unit = tid + u * 256;
        int isB = unit >> 9;
        int loc = unit & 511;
        int row = loc >> 2, ucol = loc & 3;
        uOff[u] = swz64((uint32_t)(row * 64 + ucol * 16));
        uPtr[u] = x + ((size_t)b * SS + (isB ? t0 : s0) + row) * HH + ucol * 8;
    }

    // ---- prologue: chunk 0 into buf 0 ----
    {
        char* stgp = smem + SM_STAGE;
        #pragma unroll
        for (int u = 0; u < 2; u++) {
            float4 v0 = *(const float4*)(uPtr[u]);
            float4 v1 = *(const float4*)(uPtr[u] + 4);
            cvt_store_hi(stgp, uOff[u], v0, v1);
        }
        #pragma unroll
        for (int u = 2; u < 4; u++) {
            float4 v0 = *(const float4*)(uPtr[u]);
            float4 v1 = *(const float4*)(uPtr[u] + 4);
            cvt_store_hilo(stgp, uOff[u], v0, v1);
        }
    }
    __syncthreads();

    for (int i = 0; i < NCHUNK; i++) {
        const uint32_t stg = sb + SM_STAGE + (uint32_t)(i & 1) * STAGE_BYTES;
        char* stgn = smem + SM_STAGE + ((i + 1) & 1) * STAGE_BYTES;
        const bool more = (i + 1 < NCHUNK);
        const int kn = (i + 1) * KC;

        float4 p0[2], p1[2];
        if (more) {
            #pragma unroll
            for (int u = 0; u < 2; u++) {
                p0[u] = *(const float4*)(uPtr[u] + kn);
                p1[u] = *(const float4*)(uPtr[u] + kn + 4);
            }
        }
        // ---- kk = 0 ----
        {
            const uint32_t kb = 0;
            uint32_t bh[2][4], bl[2][4];
            #pragma unroll
            for (int nb = 0; nb < 2; nb++) {
                uint32_t roff = (uint32_t)((rB + nb * 16) * 64 + kb + kBe);
                ldmx4(bh[nb], stg + B_HI + swz64(roff));
                ldmx4(bl[nb], stg + B_LO + swz64(roff));
            }
            uint32_t ah[4][4];
            #pragma unroll
            for (int mi = 0; mi < 4; mi++) {
                uint32_t roff = (uint32_t)((rA + mi * 16) * 64 + kb + kAe);
                ldmx4(ah[mi], stg + A_HI + swz64(roff));
            }
            #pragma unroll
            for (int mi = 0; mi < 4; mi++)
                #pragma unroll
                for (int ni = 0; ni < 4; ni++) {
                    mma16816(acc[mi][ni], ah[mi], &bh[ni >> 1][2 * (ni & 1)]);
                    mma16816(acc[mi][ni], ah[mi], &bl[ni >> 1][2 * (ni & 1)]);
                }
        }
        if (more) {
            #pragma unroll
            for (int u = 0; u < 2; u++)
                cvt_store_hi(stgn, uOff[u], p0[u], p1[u]);
            #pragma unroll
            for (int u = 0; u < 2; u++) {
                p0[u] = *(const float4*)(uPtr[u + 2] + kn);
                p1[u] = *(const float4*)(uPtr[u + 2] + kn + 4);
            }
        }
        // ---- kk = 1 ----
        {
            const uint32_t kb = 32;
            uint32_t bh[2][4], bl[2][4];
            #pragma unroll
            for (int nb = 0; nb < 2; nb++) {
                uint32_t roff = (uint32_t)((rB + nb * 16) * 64 + kb + kBe);
                ldmx4(bh[nb], stg + B_HI + swz64(roff));
                ldmx4(bl[nb], stg + B_LO + swz64(roff));
            }
            uint32_t ah[4][4];
            #pragma unroll
            for (int mi = 0; mi < 4; mi++) {
                uint32_t roff = (uint32_t)((rA + mi * 16) * 64 + kb + kAe);
                ldmx4(ah[mi], stg + A_HI + swz64(roff));
            }
            #pragma unroll
            for (int mi = 0; mi < 4; mi++)
                #pragma unroll
                for (int ni = 0; ni < 4; ni++) {
                    mma16816(acc[mi][ni], ah[mi], &bh[ni >> 1][2 * (ni & 1)]);
                    mma16816(acc[mi][ni], ah[mi], &bl[ni >> 1][2 * (ni & 1)]);
                }
        }
        if (more) {
            #pragma unroll
            for (int u = 0; u < 2; u++)
                cvt_store_hilo(stgn, uOff[u + 2], p0[u], p1[u]);
        }
        __syncthreads();
    }

    // ---- epilogue: W[s][t] = coef*band*G into smem (overlay on stages) ----
    float* Wb = (float*)(smem + SM_STAGE);
    #pragma unroll
    for (int mi = 0; mi < 4; mi++) {
        int r0 = wm * 64 + mi * 16 + (lane >> 2);
        int r1 = r0 + 8;
        float mq0 = mqS[r0], ma0 = maS[r0], mn0 = mnS[r0];
        float mq1 = mqS[r1], ma1 = maS[r1], mn1 = mnS[r1];
        int tn0 = turnS[r0], tn1 = turnS[r1];
        #pragma unroll
        for (int ni = 0; ni < 4; ni++) {
            int tb0 = wn * 32 + ni * 8 + (lane & 3) * 2;
            #pragma unroll
            for (int e = 0; e < 4; e++) {
                int srow = (e >> 1) ? r1 : r0;
                int tcol = tb0 + (e & 1);
                float mq_ = (e >> 1) ? mq1 : mq0;
                float ma_ = (e >> 1) ? ma1 : ma0;
                float mn_ = (e >> 1) ? mn1 : mn0;
                int tn_ = (e >> 1) ? tn1 : tn0;
                int dt = turnT[tcol] - tn_;
                float coef = fmaf(mq_, wqT[tcol], fmaf(ma_, waT[tcol], mn_ * wnT[tcol]));
                float v = (dt >= -VR && dt <= VR) ? coef * acc[mi][ni][e] : 0.f;
                Wb[srow * WSTRIDE + tcol] = v;
            }
        }
    }
    __syncthreads();
    if (tid < 128) {
        float aq = 0.f, aa = 0.f, an = 0.f;
        #pragma unroll 4
        for (int s = 0; s < 128; s++) {
            float wv = Wb[s * WSTRIDE + tid];
            aq = fmaf(sWq[s], wv, aq);
            aa = fmaf(sWa[s], wv, aa);
            an = fmaf(sWn[s], wv, an);
        }
        atomicAdd(&g_alpha[0][b * SS + t0 + tid], aq);
        atomicAdd(&g_alpha[1][b * SS + t0 + tid], aa);
        atomicAdd(&g_alpha[2][b * SS + t0 + tid], an);
        if (!diag) {
            float bq = 0.f, ba = 0.f, bn = 0.f;
            #pragma unroll 4
            for (int t = 0; t < 128; t++) {
                float wv = Wb[tid * WSTRIDE + t];
                bq = fmaf(wqT[t], wv, bq);
                ba = fmaf(waT[t], wv, ba);
                bn = fmaf(wnT[t], wv, bn);
            }
            atomicAdd(&g_alpha[0][b * SS + s0 + tid], bq);
            atomicAdd(&g_alpha[1][b * SS + s0 + tid], ba);
            atomicAdd(&g_alpha[2][b * SS + s0 + tid], bn);
        }
    }
}

// ---------------------------------------------------------------------------
// Kernel 3: FUSED self + cross streaming pass, s-split with atomics.
// ---------------------------------------------------------------------------
__global__ void __launch_bounds__(256) k3_fused(const float* __restrict__ x) {
    const int b = blockIdx.y;
    const int h = blockIdx.x * 256 + threadIdx.x;
    const int sc = blockIdx.z;
    const int sbase = sc * SCHUNK;
    const int tid = threadIdx.x;

    __shared__ float smq[SCHUNK], sma[SCHUNK], smn[SCHUNK];
    __shared__ float scq[SCHUNK], sca[SCHUNK], scn[SCHUNK];
    for (int s = tid; s < SCHUNK; s += 256) {
        int gs = b * SS + sbase + s;
        float mq = g_mask[0][gs], ma = g_mask[1][gs], mn = g_mask[2][gs];
        smq[s] = mq; sma[s] = ma; smn[s] = mn;
        scq[s] = mq * g_alpha[0][gs];
        sca[s] = ma * g_alpha[1][gs];
        scn[s] = mn * g_alpha[2][gs];
    }
    __syncthreads();

    float m0 = g_msum[0][b], m1 = g_msum[1][b], m2 = g_msum[2][b];
    float rsq = 1.f / (m0 + AVG_EPS_);
    float rsa = 1.f / (m1 + AVG_EPS_);
    float rsn = 1.f / (m2 + AVG_EPS_);
    float rcq = 1.f / (m1 + m2 + AVG_EPS_);
    float rca = 1.f / (m0 + m2 + AVG_EPS_);
    float rcn = 1.f / (m0 + m1 + AVG_EPS_);

    const float* xb = x + ((size_t)b * SS + sbase) * HH + h;
    float aq = 0.f, aa = 0.f, an = 0.f;
    float bq = 0.f, ba = 0.f, bn = 0.f;
    #pragma unroll 4
    for (int s = 0; s < SCHUNK; s++) {
        float v = xb[(size_t)s * HH];
        aq = fmaf(smq[s], v, aq);
        aa = fmaf(sma[s], v, aa);
        an = fmaf(smn[s], v, an);
        bq = fmaf(scq[s], v, bq);
        ba = fmaf(sca[s], v, ba);
        bn = fmaf(scn[s], v, bn);
    }
    atomicAdd(&g_self[0][b * HH + h], aq * rsq);
    atomicAdd(&g_self[1][b * HH + h], aa * rsa);
    atomicAdd(&g_self[2][b * HH + h], an * rsn);
    atomicAdd(&g_cross[0][b * HH + h], bq * rcq);
    atomicAdd(&g_cross[1][b * HH + h], ba * rca);
    atomicAdd(&g_cross[2][b * HH + h], bn * rcn);
}

// ---------------------------------------------------------------------------
// Kernel 4: per-batch cosine logits; write q/a/n_output rows.
// ---------------------------------------------------------------------------
__global__ void k4_logits(float* __restrict__ out) {
    const int b = blockIdx.x;
    const int tid = threadIdx.x;
    float p[9];
    #pragma unroll
    for (int k = 0; k < 9; k++) p[k] = 0.f;
    for (int h = tid; h < HH; h += blockDim.x) {
        #pragma unroll
        for (int m = 0; m < 3; m++) {
            float sv = g_self[m][b * HH + h];
            float cv = g_cross[m][b * HH + h];
            p[m * 3 + 0] = fmaf(sv, cv, p[m * 3 + 0]);
            p[m * 3 + 1] = fmaf(sv, sv, p[m * 3 + 1]);
            p[m * 3 + 2] = fmaf(cv, cv, p[m * 3 + 2]);
        }
    }
    #pragma unroll
    for (int k = 0; k < 9; k++)
        #pragma unroll
        for (int o = 16; o > 0; o >>= 1)
            p[k] += __shfl_down_sync(0xffffffffu, p[k], o);
    __shared__ float red[9][8];
    if ((tid & 31) == 0) {
        int w = tid >> 5;
        #pragma unroll
        for (int k = 0; k < 9; k++) red[k][w] = p[k];
    }
    __syncthreads();
    if (tid == 0) {
        #pragma unroll
        for (int m = 0; m < 3; m++) {
            float dot = 0.f, n1 = 0.f, n2 = 0.f;
            for (int w = 0; w < 8; w++) {
                dot += red[m * 3 + 0][w];
                n1  += red[m * 3 + 1][w];
                n2  += red[m * 3 + 2][w];
            }
            float nx = fmaxf(sqrtf(n1), COS_EPS_);
            float ny = fmaxf(sqrtf(n2), COS_EPS_);
            float c = dot / (nx * ny);
            g_logits[m][b] = (c == 1.0f) ? __int_as_float(0x7fc00000) : c / TEMP_;
        }
    }
    if (b % SN == 0) {
        int g = b / SN;
        for (int h = tid; h < HH; h += blockDim.x) {
            out[1 + 0 * NG * HH + g * HH + h] = g_self[0][b * HH + h];
            out[1 + 1 * NG * HH + g * HH + h] = g_self[1][b * HH + h];
            out[1 + 2 * NG * HH + g * HH + h] = g_self[2][b * HH + h];
        }
    }
}

// ---------------------------------------------------------------------------
// Kernel 5: log-softmax + nanmean loss (tiny).
// ---------------------------------------------------------------------------
__global__ void k5_loss(const float* __restrict__ labels, float* __restrict__ out) {
    if (threadIdx.x != 0 || blockIdx.x != 0) return;
    float losses[3];
    for (int m = 0; m < 3; m++) {
        float sum = 0.f;
        int cnt = 0;
        for (int g = 0; g < NG; g++) {
            float l[SN];
            bool bad = false;
            for (int j = 0; j < SN; j++) {
                l[j] = g_logits[m][g * SN + j];
                if (isnan(l[j])) bad = true;
            }
            if (bad) continue;
            float mx = l[0];
            for (int j = 1; j < SN; j++) mx = fmaxf(mx, l[j]);
            float se = 0.f;
            for (int j = 0; j < SN; j++) se += expf(l[j] - mx);
            float lse = mx + logf(se);
            for (int j = 0; j < SN; j++) sum += (l[j] - lse) * labels[g * SN + j];
            cnt += SN;
        }
        losses[m] = -(sum / (float)cnt);
    }
    out[0] = (losses[1] + losses[0] + losses[2]) / 3.0f;
}

// ---------------------------------------------------------------------------
extern "C" void kernel_launch(void* const* d_in, const int* in_sizes, int n_in,
                              void* d_out, int out_size) {
    const float* x      = (const float*)d_in[0];
    const float* am     = (const float*)d_in[1];
    const float* labels = (const float*)d_in[2];
    const int*   qa     = (const int*)d_in[3];
    const int*   turn   = (const int*)d_in[4];
    float* out = (float*)d_out;

    cudaFuncSetAttribute(k2_mma, cudaFuncAttributeMaxDynamicSharedMemorySize, SMEM_BYTES);

    k0_masks<<<dim3(NB, 2), 256>>>(am, qa);
    k2_mma<<<dim3(SS / TN, SS / TM, NB), 256, SMEM_BYTES>>>(x, turn);
    k3_fused<<<dim3(3, NB, SPLITS), 256>>>(x);
    k4_logits<<<NB, 256>>>(out);
    k5_loss<<<1, 32>>>(labels, out);
}

// round 11
// speedup vs baseline: 2.8995x; 1.2318x over previous
#include <cuda_runtime.h>
#include <cuda_fp16.h>
#include <math.h>
#include <cstdint>

namespace {
constexpr int NB = 72;
constexpr int SS = 512;
constexpr int HH = 768;
constexpr int NG = 8;
constexpr int SN = 9;
constexpr float TEMP_ = 0.07f;
constexpr float AVG_EPS_ = 1e-6f;
constexpr float COS_EPS_ = 1e-8f;
constexpr int VR = 2;
constexpr int SPLITS = 8;
constexpr int SCHUNK = SS / SPLITS;  // 64

// ---- gram tiling ----
constexpr int TM = 128, TN = 128, KC = 32;
constexpr int NCHUNK = HH / KC;  // 24

// ---- smem layout for gram kernel ----
constexpr int SM_TURNT = 0;      // int[128]
constexpr int SM_TURNS = 512;
constexpr int SM_WQT   = 1024;   // t-side w
constexpr int SM_WAT   = 1536;
constexpr int SM_WNT   = 2048;
constexpr int SM_MQS   = 2560;   // s-side raw masks
constexpr int SM_MAS   = 3072;
constexpr int SM_MNS   = 3584;
constexpr int SM_SWQ   = 4096;   // s-side w
constexpr int SM_SWA   = 4608;
constexpr int SM_SWN   = 5120;
constexpr int SM_STAGE = 6144;   // 2 x 16KB stage (A_HI, B_HI)
constexpr int STAGE_BYTES = 16384;
constexpr int A_HI = 0, B_HI = 8192;
constexpr int WSTRIDE = 129;     // W overlay on stages (post-loop), 66048 B
constexpr int SMEM_BYTES = SM_STAGE + 128 * WSTRIDE * 4;  // 72192
}

// Scratch (no allocations allowed)
__device__ float g_mask[3][NB * SS];
__device__ float g_msum[3][NB];
__device__ float g_self[3][NB * HH];
__device__ float g_alpha[3][NB * SS];
__device__ float g_cross[3][NB * HH];
__device__ float g_logits[3][NB];

// ===================== helpers =====================
__device__ __forceinline__ uint32_t smem_u32(const void* p) {
    uint32_t a;
    asm("{ .reg .u64 t; cvta.to.shared.u64 t, %1; cvt.u32.u64 %0, t; }" : "=r"(a) : "l"(p));
    return a;
}
__device__ __forceinline__ uint32_t swz64(uint32_t off) { return off ^ ((off >> 3) & 0x30); }

__device__ __forceinline__ void ldmx4(uint32_t* r, uint32_t addr) {
    asm volatile("ldmatrix.sync.aligned.m8n8.x4.shared.b16 {%0,%1,%2,%3}, [%4];"
                 : "=r"(r[0]), "=r"(r[1]), "=r"(r[2]), "=r"(r[3]) : "r"(addr));
}
__device__ __forceinline__ void mma16816(float* d, const uint32_t* a, const uint32_t* b) {
    asm volatile(
        "mma.sync.aligned.m16n8k16.row.col.f32.f16.f16.f32 "
        "{%0,%1,%2,%3}, {%4,%5,%6,%7}, {%8,%9}, {%0,%1,%2,%3};"
        : "+f"(d[0]), "+f"(d[1]), "+f"(d[2]), "+f"(d[3])
        : "r"(a[0]), "r"(a[1]), "r"(a[2]), "r"(a[3]), "r"(b[0]), "r"(b[1]));
}

__device__ __forceinline__ uint32_t h2u(__half2 h) {
    return *reinterpret_cast<uint32_t*>(&h);
}

// fp32x8 -> fp16 and store swizzled
__device__ __forceinline__ void cvt_store_hi(char* stgp, int base, uint32_t off,
                                             const float4& v0, const float4& v1) {
    uint4 Hi;
    Hi.x = h2u(__floats2half2_rn(v0.x, v0.y));
    Hi.y = h2u(__floats2half2_rn(v0.z, v0.w));
    Hi.z = h2u(__floats2half2_rn(v1.x, v1.y));
    Hi.w = h2u(__floats2half2_rn(v1.z, v1.w));
    *(uint4*)(stgp + base + off) = Hi;
}

// ---------------------------------------------------------------------------
// Kernel 0: grid (NB, 2). part 0: masks + sums + zero alpha. part 1: zero h-bufs.
// ---------------------------------------------------------------------------
__global__ void k0_masks(const float* __restrict__ am,
                         const int* __restrict__ qa) {
    const int b = blockIdx.x;
    const int tid = threadIdx.x;
    if (blockIdx.y == 1) {
        for (int h = tid; h < HH; h += blockDim.x) {
            #pragma unroll
            for (int m = 0; m < 3; m++) {
                g_self[m][b * HH + h] = 0.f;
                g_cross[m][b * HH + h] = 0.f;
            }
        }
        return;
    }
    __shared__ float red[3][8];
    float pq = 0.f, pa = 0.f, pn = 0.f;
    for (int s = tid; s < SS; s += blockDim.x) {
        int q = qa[b * SS + s];
        float a = am[b * SS + s];
        float mq = (q == 1 || q == 2) ? a : 0.f;
        float ma = (q == 0 || q == 2) ? a : 0.f;
        float mn = (q == 3) ? a : 0.f;
        g_mask[0][b * SS + s] = mq;
        g_mask[1][b * SS + s] = ma;
        g_mask[2][b * SS + s] = mn;
        g_alpha[0][b * SS + s] = 0.f;
        g_alpha[1][b * SS + s] = 0.f;
        g_alpha[2][b * SS + s] = 0.f;
        pq += mq; pa += ma; pn += mn;
    }
    #pragma unroll
    for (int o = 16; o > 0; o >>= 1) {
        pq += __shfl_down_sync(0xffffffffu, pq, o);
        pa += __shfl_down_sync(0xffffffffu, pa, o);
        pn += __shfl_down_sync(0xffffffffu, pn, o);
    }
    if ((tid & 31) == 0) {
        int w = tid >> 5;
        red[0][w] = pq; red[1][w] = pa; red[2][w] = pn;
    }
    __syncthreads();
    if (tid == 0) {
        int nw = blockDim.x >> 5;
        float s0 = 0.f, s1 = 0.f, s2 = 0.f;
        for (int w = 0; w < nw; w++) { s0 += red[0][w]; s1 += red[1][w]; s2 += red[2][w]; }
        g_msum[0][b] = s0; g_msum[1][b] = s1; g_msum[2][b] = s2;
    }
}

// ---------------------------------------------------------------------------
// Kernel 2: banded SYMMETRIC Gram via mma.sync fp16 SINGLE pass:
//   G = A_hi * B_hi   (drops A_lo*B + A_hi*B_lo ~ 2^-11-scale; final ~3e-5)
// Diagonal tiles reuse the A plane for B (load dedup).
// KC=32, SW64 stage. Upper triangle; dual gemv epilogue mirrors.
// ---------------------------------------------------------------------------
__global__ void __launch_bounds__(256, 2)
k2_mma(const float* __restrict__ x, const int* __restrict__ turn) {
    const int b = blockIdx.z;
    const int I = blockIdx.y, J = blockIdx.x;
    if (J < I) return;
    const int s0 = I * TM, t0 = J * TN;
    const int* tb = turn + b * SS;
    if (tb[t0] - tb[s0 + TM - 1] > VR) return;
    const bool diag = (I == J);

    extern __shared__ char smem[];
    const uint32_t sb = smem_u32(smem);
    const int tid = threadIdx.x, wid = tid >> 5, lane = tid & 31;
    const int wm = wid & 1, wn = wid >> 1;

    int*   turnT = (int*)(smem + SM_TURNT);
    int*   turnS = (int*)(smem + SM_TURNS);
    float* wqT = (float*)(smem + SM_WQT);
    float* waT = (float*)(smem + SM_WAT);
    float* wnT = (float*)(smem + SM_WNT);
    float* mqS = (float*)(smem + SM_MQS);
    float* maS = (float*)(smem + SM_MAS);
    float* mnS = (float*)(smem + SM_MNS);
    float* sWq = (float*)(smem + SM_SWQ);
    float* sWa = (float*)(smem + SM_SWA);
    float* sWn = (float*)(smem + SM_SWN);
    if (tid < 128) {
        int gt = b * SS + t0 + tid;
        float mq = g_mask[0][gt], ma = g_mask[1][gt], mn = g_mask[2][gt];
        wqT[tid] = ma + mn; waT[tid] = mq + mn; wnT[tid] = mq + ma;
        turnT[tid] = tb[t0 + tid];
        int gs = b * SS + s0 + tid;
        float mqs = g_mask[0][gs], mas = g_mask[1][gs], mns = g_mask[2][gs];
        mqS[tid] = mqs; maS[tid] = mas; mnS[tid] = mns;
        sWq[tid] = mas + mns; sWa[tid] = mqs + mns; sWn[tid] = mqs + mas;
        turnS[tid] = tb[s0 + tid];
    }

    float acc[4][4][4];
    #pragma unroll
    for (int mi = 0; mi < 4; mi++)
        #pragma unroll
        for (int ni = 0; ni < 4; ni++)
            #pragma unroll
            for (int e = 0; e < 4; e++) acc[mi][ni][e] = 0.f;

    const int rA = wm * 64 + (lane & 15);
    const int kAe = (lane >> 4) * 16;
    const int rB = wn * 32 + ((lane >> 4) & 1) * 8 + (lane & 7);
    const int kBe = ((lane >> 3) & 1) * 16;

    // B tile base: diag reuses the A plane
    const uint32_t bBase = diag ? (uint32_t)A_HI : (uint32_t)B_HI;

    // per-unit constants (unit = tid + u*256; u=0..3). u<2 -> A tile, u>=2 -> B tile.
    uint32_t uOff[4];
    const float* uPtr[4];
    #pragma unroll
    for (int u = 0; u < 4; u++) {
        int unit = tid + u * 256;
        int isB = unit >> 9;
        int loc = unit & 511;
        int row = loc >> 2, ucol = loc & 3;
        uOff[u] = swz64((uint32_t)(row * 64 + ucol * 16));
        uPtr[u] = x + ((size_t)b * SS + (isB ? t0 : s0) + row) * HH + ucol * 8;
    }

    // ---- prologue: chunk 0 into buf 0 ----
    {
        char* stgp = smem + SM_STAGE;
        #pragma unroll
        for (int u = 0; u < 2; u++) {
            float4 v0 = *(const float4*)(uPtr[u]);
            float4 v1 = *(const float4*)(uPtr[u] + 4);
            cvt_store_hi(stgp, A_HI, uOff[u], v0, v1);
        }
        if (!diag) {
            #pragma unroll
            for (int u = 2; u < 4; u++) {
                float4 v0 = *(const float4*)(uPtr[u]);
                float4 v1 = *(const float4*)(uPtr[u] + 4);
                cvt_store_hi(stgp, B_HI, uOff[u], v0, v1);
            }
        }
    }
    __syncthreads();

    for (int i = 0; i < NCHUNK; i++) {
        const uint32_t stg = sb + SM_STAGE + (uint32_t)(i & 1) * STAGE_BYTES;
        char* stgn = smem + SM_STAGE + ((i + 1) & 1) * STAGE_BYTES;
        const bool more = (i + 1 < NCHUNK);
        const int kn = (i + 1) * KC;

        float4 p0[2], p1[2];
        if (more) {
            #pragma unroll
            for (int u = 0; u < 2; u++) {
                p0[u] = *(const float4*)(uPtr[u] + kn);
                p1[u] = *(const float4*)(uPtr[u] + kn + 4);
            }
        }
        // ---- kk = 0 ----
        {
            const uint32_t kb = 0;
            uint32_t bh[2][4];
            #pragma unroll
            for (int nb = 0; nb < 2; nb++) {
                uint32_t roff = (uint32_t)((rB + nb * 16) * 64 + kb + kBe);
                ldmx4(bh[nb], stg + bBase + swz64(roff));
            }
            uint32_t ah[4][4];
            #pragma unroll
            for (int mi = 0; mi < 4; mi++) {
                uint32_t roff = (uint32_t)((rA + mi * 16) * 64 + kb + kAe);
                ldmx4(ah[mi], stg + A_HI + swz64(roff));
            }
            #pragma unroll
            for (int mi = 0; mi < 4; mi++)
                #pragma unroll
                for (int ni = 0; ni < 4; ni++)
                    mma16816(acc[mi][ni], ah[mi], &bh[ni >> 1][2 * (ni & 1)]);
        }
        if (more) {
            #pragma unroll
            for (int u = 0; u < 2; u++)
                cvt_store_hi(stgn, A_HI, uOff[u], p0[u], p1[u]);
            if (!diag) {
                #pragma unroll
                for (int u = 0; u < 2; u++) {
                    p0[u] = *(const float4*)(uPtr[u + 2] + kn);
                    p1[u] = *(const float4*)(uPtr[u + 2] + kn + 4);
                }
            }
        }
        // ---- kk = 1 ----
        {
            const uint32_t kb = 32;
            uint32_t bh[2][4];
            #pragma unroll
            for (int nb = 0; nb < 2; nb++) {
                uint32_t roff = (uint32_t)((rB + nb * 16) * 64 + kb + kBe);
                ldmx4(bh[nb], stg + bBase + swz64(roff));
            }
            uint32_t ah[4][4];
            #pragma unroll
            for (int mi = 0; mi < 4; mi++) {
                uint32_t roff = (uint32_t)((rA + mi * 16) * 64 + kb + kAe);
                ldmx4(ah[mi], stg + A_HI + swz64(roff));
            }
            #pragma unroll
            for (int mi = 0; mi < 4; mi++)
                #pragma unroll
                for (int ni = 0; ni < 4; ni++)
                    mma16816(acc[mi][ni], ah[mi], &bh[ni >> 1][2 * (ni & 1)]);
        }
        if (more && !diag) {
            #pragma unroll
            for (int u = 0; u < 2; u++)
                cvt_store_hi(stgn, B_HI, uOff[u + 2], p0[u], p1[u]);
        }
        __syncthreads();
    }

    // ---- epilogue: W[s][t] = coef*band*G into smem (overlay on stages) ----
    float* Wb = (float*)(smem + SM_STAGE);
    #pragma unroll
    for (int mi = 0; mi < 4; mi++) {
        int r0 = wm * 64 + mi * 16 + (lane >> 2);
        int r1 = r0 + 8;
        float mq0 = mqS[r0], ma0 = maS[r0], mn0 = mnS[r0];
        float mq1 = mqS[r1], ma1 = maS[r1], mn1 = mnS[r1];
        int tn0 = turnS[r0], tn1 = turnS[r1];
        #pragma unroll
        for (int ni = 0; ni < 4; ni++) {
            int tb0 = wn * 32 + ni * 8 + (lane & 3) * 2;
            #pragma unroll
            for (int e = 0; e < 4; e++) {
                int srow = (e >> 1) ? r1 : r0;
                int tcol = tb0 + (e & 1);
                float mq_ = (e >> 1) ? mq1 : mq0;
                float ma_ = (e >> 1) ? ma1 : ma0;
                float mn_ = (e >> 1) ? mn1 : mn0;
                int tn_ = (e >> 1) ? tn1 : tn0;
                int dt = turnT[tcol] - tn_;
                float coef = fmaf(mq_, wqT[tcol], fmaf(ma_, waT[tcol], mn_ * wnT[tcol]));
                float v = (dt >= -VR && dt <= VR) ? coef * acc[mi][ni][e] : 0.f;
                Wb[srow * WSTRIDE + tcol] = v;
            }
        }
    }
    __syncthreads();
    if (tid < 128) {
        float aq = 0.f, aa = 0.f, an = 0.f;
        #pragma unroll 4
        for (int s = 0; s < 128; s++) {
            float wv = Wb[s * WSTRIDE + tid];
            aq = fmaf(sWq[s], wv, aq);
            aa = fmaf(sWa[s], wv, aa);
            an = fmaf(sWn[s], wv, an);
        }
        atomicAdd(&g_alpha[0][b * SS + t0 + tid], aq);
        atomicAdd(&g_alpha[1][b * SS + t0 + tid], aa);
        atomicAdd(&g_alpha[2][b * SS + t0 + tid], an);
        if (!diag) {
            float bq = 0.f, ba = 0.f, bn = 0.f;
            #pragma unroll 4
            for (int t = 0; t < 128; t++) {
                float wv = Wb[tid * WSTRIDE + t];
                bq = fmaf(wqT[t], wv, bq);
                ba = fmaf(waT[t], wv, ba);
                bn = fmaf(wnT[t], wv, bn);
            }
            atomicAdd(&g_alpha[0][b * SS + s0 + tid], bq);
            atomicAdd(&g_alpha[1][b * SS + s0 + tid], ba);
            atomicAdd(&g_alpha[2][b * SS + s0 + tid], bn);
        }
    }
}

// ---------------------------------------------------------------------------
// Kernel 3: FUSED self + cross streaming pass, s-split with atomics.
// ---------------------------------------------------------------------------
__global__ void __launch_bounds__(256) k3_fused(const float* __restrict__ x) {
    const int b = blockIdx.y;
    const int h = blockIdx.x * 256 + threadIdx.x;
    const int sc = blockIdx.z;
    const int sbase = sc * SCHUNK;
    const int tid = threadIdx.x;

    __shared__ float smq[SCHUNK], sma[SCHUNK], smn[SCHUNK];
    __shared__ float scq[SCHUNK], sca[SCHUNK], scn[SCHUNK];
    for (int s = tid; s < SCHUNK; s += 256) {
        int gs = b * SS + sbase + s;
        float mq = g_mask[0][gs], ma = g_mask[1][gs], mn = g_mask[2][gs];
        smq[s] = mq; sma[s] = ma; smn[s] = mn;
        scq[s] = mq * g_alpha[0][gs];
        sca[s] = ma * g_alpha[1][gs];
        scn[s] = mn * g_alpha[2][gs];
    }
    __syncthreads();

    float m0 = g_msum[0][b], m1 = g_msum[1][b], m2 = g_msum[2][b];
    float rsq = 1.f / (m0 + AVG_EPS_);
    float rsa = 1.f / (m1 + AVG_EPS_);
    float rsn = 1.f / (m2 + AVG_EPS_);
    float rcq = 1.f / (m1 + m2 + AVG_EPS_);
    float rca = 1.f / (m0 + m2 + AVG_EPS_);
    float rcn = 1.f / (m0 + m1 + AVG_EPS_);

    const float* xb = x + ((size_t)b * SS + sbase) * HH + h;
    float aq = 0.f, aa = 0.f, an = 0.f;
    float bq = 0.f, ba = 0.f, bn = 0.f;
    #pragma unroll 4
    for (int s = 0; s < SCHUNK; s++) {
        float v = xb[(size_t)s * HH];
        aq = fmaf(smq[s], v, aq);
        aa = fmaf(sma[s], v, aa);
        an = fmaf(smn[s], v, an);
        bq = fmaf(scq[s], v, bq);
        ba = fmaf(sca[s], v, ba);
        bn = fmaf(scn[s], v, bn);
    }
    atomicAdd(&g_self[0][b * HH + h], aq * rsq);
    atomicAdd(&g_self[1][b * HH + h], aa * rsa);
    atomicAdd(&g_self[2][b * HH + h], an * rsn);
    atomicAdd(&g_cross[0][b * HH + h], bq * rcq);
    atomicAdd(&g_cross[1][b * HH + h], ba * rca);
    atomicAdd(&g_cross[2][b * HH + h], bn * rcn);
}

// ---------------------------------------------------------------------------
// Kernel 4: per-batch cosine logits; write q/a/n_output rows.
// ---------------------------------------------------------------------------
__global__ void k4_logits(float* __restrict__ out) {
    const int b = blockIdx.x;
    const int tid = threadIdx.x;
    float p[9];
    #pragma unroll
    for (int k = 0; k < 9; k++) p[k] = 0.f;
    for (int h = tid; h < HH; h += blockDim.x) {
        #pragma unroll
        for (int m = 0; m < 3; m++) {
            float sv = g_self[m][b * HH + h];
            float cv = g_cross[m][b * HH + h];
            p[m * 3 + 0] = fmaf(sv, cv, p[m * 3 + 0]);
            p[m * 3 + 1] = fmaf(sv, sv, p[m * 3 + 1]);
            p[m * 3 + 2] = fmaf(cv, cv, p[m * 3 + 2]);
        }
    }
    #pragma unroll
    for (int k = 0; k < 9; k++)
        #pragma unroll
        for (int o = 16; o > 0; o >>= 1)
            p[k] += __shfl_down_sync(0xffffffffu, p[k], o);
    __shared__ float red[9][8];
    if ((tid & 31) == 0) {
        int w = tid >> 5;
        #pragma unroll
        for (int k = 0; k < 9; k++) red[k][w] = p[k];
    }
    __syncthreads();
    if (tid == 0) {
        #pragma unroll
        for (int m = 0; m < 3; m++) {
            float dot = 0.f, n1 = 0.f, n2 = 0.f;
            for (int w = 0; w < 8; w++) {
                dot += red[m * 3 + 0][w];
                n1  += red[m * 3 + 1][w];
                n2  += red[m * 3 + 2][w];
            }
            float nx = fmaxf(sqrtf(n1), COS_EPS_);
            float ny = fmaxf(sqrtf(n2), COS_EPS_);
            float c = dot / (nx * ny);
            g_logits[m][b] = (c == 1.0f) ? __int_as_float(0x7fc00000) : c / TEMP_;
        }
    }
    if (b % SN == 0) {
        int g = b / SN;
        for (int h = tid; h < HH; h += blockDim.x) {
            out[1 + 0 * NG * HH + g * HH + h] = g_self[0][b * HH + h];
            out[1 + 1 * NG * HH + g * HH + h] = g_self[1][b * HH + h];
            out[1 + 2 * NG * HH + g * HH + h] = g_self[2][b * HH + h];
        }
    }
}

// ---------------------------------------------------------------------------
// Kernel 5: log-softmax + nanmean loss (tiny).
// ---------------------------------------------------------------------------
__global__ void k5_loss(const float* __restrict__ labels, float* __restrict__ out) {
    if (threadIdx.x != 0 || blockIdx.x != 0) return;
    float losses[3];
    for (int m = 0; m < 3; m++) {
        float sum = 0.f;
        int cnt = 0;
        for (int g = 0; g < NG; g++) {
            float l[SN];
            bool bad = false;
            for (int j = 0; j < SN; j++) {
                l[j] = g_logits[m][g * SN + j];
                if (isnan(l[j])) bad = true;
            }
            if (bad) continue;
            float mx = l[0];
            for (int j = 1; j < SN; j++) mx = fmaxf(mx, l[j]);
            float se = 0.f;
            for (int j = 0; j < SN; j++) se += expf(l[j] - mx);
            float lse = mx + logf(se);
            for (int j = 0; j < SN; j++) sum += (l[j] - lse) * labels[g * SN + j];
            cnt += SN;
        }
        losses[m] = -(sum / (float)cnt);
    }
    out[0] = (losses[1] + losses[0] + losses[2]) / 3.0f;
}

// ---------------------------------------------------------------------------
extern "C" void kernel_launch(void* const* d_in, const int* in_sizes, int n_in,
                              void* d_out, int out_size) {
    const float* x      = (const float*)d_in[0];
    const float* am     = (const float*)d_in[1];
    const float* labels = (const float*)d_in[2];
    const int*   qa     = (const int*)d_in[3];
    const int*   turn   = (const int*)d_in[4];
    float* out = (float*)d_out;

    cudaFuncSetAttribute(k2_mma, cudaFuncAttributeMaxDynamicSharedMemorySize, SMEM_BYTES);

    k0_masks<<<dim3(NB, 2), 256>>>(am, qa);
    k2_mma<<<dim3(SS / TN, SS / TM, NB), 256, SMEM_BYTES>>>(x, turn);
    k3_fused<<<dim3(3, NB, SPLITS), 256>>>(x);
    k4_logits<<<NB, 256>>>(out);
    k5_loss<<<1, 32>>>(labels, out);
}

// round 12
// speedup vs baseline: 3.1063x; 1.0713x over previous
#include <cuda_runtime.h>
#include <cuda_fp16.h>
#include <math.h>
#include <cstdint>

namespace {
constexpr int NB = 72;
constexpr int SS = 512;
constexpr int HH = 768;
constexpr int NG = 8;
constexpr int SN = 9;
constexpr float TEMP_ = 0.07f;
constexpr float AVG_EPS_ = 1e-6f;
constexpr float COS_EPS_ = 1e-8f;
constexpr int VR = 2;
constexpr int SPLITS = 8;
constexpr int SCHUNK = SS / SPLITS;  // 64

// ---- gram tiling ----
constexpr int TM = 128, TN = 128, KC = 64;
constexpr int NCHUNK = HH / KC;  // 12

// ---- smem layout for gram kernel ----
constexpr int SM_TURNT = 0;      // int[128]
constexpr int SM_TURNS = 512;
constexpr int SM_WQT   = 1024;   // t-side w
constexpr int SM_WAT   = 1536;
constexpr int SM_WNT   = 2048;
constexpr int SM_MQS   = 2560;   // s-side raw masks
constexpr int SM_MAS   = 3072;
constexpr int SM_MNS   = 3584;
constexpr int SM_SWQ   = 4096;   // s-side w
constexpr int SM_SWA   = 4608;
constexpr int SM_SWN   = 5120;
constexpr int SM_STAGE = 6144;   // 2 x 32KB stage (A_HI, B_HI), fp16 SW128
constexpr int STAGE_BYTES = 32768;
constexpr int A_HI = 0, B_HI = 16384;
constexpr int WSTRIDE = 129;     // W overlay on stages (post-loop), 66048 B
constexpr int SMEM_BYTES = SM_STAGE + 128 * WSTRIDE * 4;  // 72192 -> 2 CTAs/SM
}

// Scratch (no allocations allowed)
__device__ float g_mask[3][NB * SS];
__device__ float g_msum[3][NB];
__device__ float g_self[3][NB * HH];
__device__ float g_alpha[3][NB * SS];
__device__ float g_cross[3][NB * HH];
__device__ float g_logits[3][NB];

// ===================== helpers =====================
__device__ __forceinline__ uint32_t smem_u32(const void* p) {
    uint32_t a;
    asm("{ .reg .u64 t; cvta.to.shared.u64 t, %1; cvt.u32.u64 %0, t; }" : "=r"(a) : "l"(p));
    return a;
}
__device__ __forceinline__ uint32_t swz128(uint32_t off) { return off ^ ((off >> 3) & 0x70); }

__device__ __forceinline__ void ldmx4(uint32_t* r, uint32_t addr) {
    asm volatile("ldmatrix.sync.aligned.m8n8.x4.shared.b16 {%0,%1,%2,%3}, [%4];"
                 : "=r"(r[0]), "=r"(r[1]), "=r"(r[2]), "=r"(r[3]) : "r"(addr));
}
__device__ __forceinline__ void mma16816(float* d, const uint32_t* a, const uint32_t* b) {
    asm volatile(
        "mma.sync.aligned.m16n8k16.row.col.f32.f16.f16.f32 "
        "{%0,%1,%2,%3}, {%4,%5,%6,%7}, {%8,%9}, {%0,%1,%2,%3};"
        : "+f"(d[0]), "+f"(d[1]), "+f"(d[2]), "+f"(d[3])
        : "r"(a[0]), "r"(a[1]), "r"(a[2]), "r"(a[3]), "r"(b[0]), "r"(b[1]));
}

__device__ __forceinline__ uint32_t h2u(__half2 h) {
    return *reinterpret_cast<uint32_t*>(&h);
}

// fp32x8 -> fp16 and store swizzled
__device__ __forceinline__ void cvt_store_hi(char* stgp, int base, uint32_t off,
                                             const float4& v0, const float4& v1) {
    uint4 Hi;
    Hi.x = h2u(__floats2half2_rn(v0.x, v0.y));
    Hi.y = h2u(__floats2half2_rn(v0.z, v0.w));
    Hi.z = h2u(__floats2half2_rn(v1.x, v1.y));
    Hi.w = h2u(__floats2half2_rn(v1.z, v1.w));
    *(uint4*)(stgp + base + off) = Hi;
}

// ---------------------------------------------------------------------------
// Kernel 0: grid (NB, 2). part 0: masks + sums + zero alpha. part 1: zero h-bufs.
// ---------------------------------------------------------------------------
__global__ void k0_masks(const float* __restrict__ am,
                         const int* __restrict__ qa) {
    const int b = blockIdx.x;
    const int tid = threadIdx.x;
    if (blockIdx.y == 1) {
        for (int h = tid; h < HH; h += blockDim.x) {
            #pragma unroll
            for (int m = 0; m < 3; m++) {
                g_self[m][b * HH + h] = 0.f;
                g_cross[m][b * HH + h] = 0.f;
            }
        }
        return;
    }
    __shared__ float red[3][8];
    float pq = 0.f, pa = 0.f, pn = 0.f;
    for (int s = tid; s < SS; s += blockDim.x) {
        int q = qa[b * SS + s];
        float a = am[b * SS + s];
        float mq = (q == 1 || q == 2) ? a : 0.f;
        float ma = (q == 0 || q == 2) ? a : 0.f;
        float mn = (q == 3) ? a : 0.f;
        g_mask[0][b * SS + s] = mq;
        g_mask[1][b * SS + s] = ma;
        g_mask[2][b * SS + s] = mn;
        g_alpha[0][b * SS + s] = 0.f;
        g_alpha[1][b * SS + s] = 0.f;
        g_alpha[2][b * SS + s] = 0.f;
        pq += mq; pa += ma; pn += mn;
    }
    #pragma unroll
    for (int o = 16; o > 0; o >>= 1) {
        pq += __shfl_down_sync(0xffffffffu, pq, o);
        pa += __shfl_down_sync(0xffffffffu, pa, o);
        pn += __shfl_down_sync(0xffffffffu, pn, o);
    }
    if ((tid & 31) == 0) {
        int w = tid >> 5;
        red[0][w] = pq; red[1][w] = pa; red[2][w] = pn;
    }
    __syncthreads();
    if (tid == 0) {
        int nw = blockDim.x >> 5;
        float s0 = 0.f, s1 = 0.f, s2 = 0.f;
        for (int w = 0; w < nw; w++) { s0 += red[0][w]; s1 += red[1][w]; s2 += red[2][w]; }
        g_msum[0][b] = s0; g_msum[1][b] = s1; g_msum[2][b] = s2;
    }
}

// ---------------------------------------------------------------------------
// Kernel 2: banded SYMMETRIC Gram, single-pass fp16 mma, KC=64 SW128 stage.
// Diagonal tiles reuse the A plane. Upper triangle; dual gemv epilogue.
// ---------------------------------------------------------------------------
__global__ void __launch_bounds__(256, 2)
k2_mma(const float* __restrict__ x, const int* __restrict__ turn) {
    const int b = blockIdx.z;
    const int I = blockIdx.y, J = blockIdx.x;
    if (J < I) return;
    const int s0 = I * TM, t0 = J * TN;
    const int* tb = turn + b * SS;
    if (tb[t0] - tb[s0 + TM - 1] > VR) return;
    const bool diag = (I == J);

    extern __shared__ char smem[];
    const uint32_t sb = smem_u32(smem);
    const int tid = threadIdx.x, wid = tid >> 5, lane = tid & 31;
    const int wm = wid & 1, wn = wid >> 1;

    int*   turnT = (int*)(smem + SM_TURNT);
    int*   turnS = (int*)(smem + SM_TURNS);
    float* wqT = (float*)(smem + SM_WQT);
    float* waT = (float*)(smem + SM_WAT);
    float* wnT = (float*)(smem + SM_WNT);
    float* mqS = (float*)(smem + SM_MQS);
    float* maS = (float*)(smem + SM_MAS);
    float* mnS = (float*)(smem + SM_MNS);
    float* sWq = (float*)(smem + SM_SWQ);
    float* sWa = (float*)(smem + SM_SWA);
    float* sWn = (float*)(smem + SM_SWN);
    if (tid < 128) {
        int gt = b * SS + t0 + tid;
        float mq = g_mask[0][gt], ma = g_mask[1][gt], mn = g_mask[2][gt];
        wqT[tid] = ma + mn; waT[tid] = mq + mn; wnT[tid] = mq + ma;
        turnT[tid] = tb[t0 + tid];
        int gs = b * SS + s0 + tid;
        float mqs = g_mask[0][gs], mas = g_mask[1][gs], mns = g_mask[2][gs];
        mqS[tid] = mqs; maS[tid] = mas; mnS[tid] = mns;
        sWq[tid] = mas + mns; sWa[tid] = mqs + mns; sWn[tid] = mqs + mas;
        turnS[tid] = tb[s0 + tid];
    }

    float acc[4][4][4];
    #pragma unroll
    for (int mi = 0; mi < 4; mi++)
        #pragma unroll
        for (int ni = 0; ni < 4; ni++)
            #pragma unroll
            for (int e = 0; e < 4; e++) acc[mi][ni][e] = 0.f;

    const int rA = wm * 64 + (lane & 15);
    const int kAe = (lane >> 4) * 16;
    const int rB = wn * 32 + ((lane >> 4) & 1) * 8 + (lane & 7);
    const int kBe = ((lane >> 3) & 1) * 16;

    const uint32_t bBase = diag ? (uint32_t)A_HI : (uint32_t)B_HI;

    // per-unit constants (unit = tid + u*256; u=0..7). u<4 -> A tile, u>=4 -> B tile.
    uint32_t uOff[8];
    const float* uPtr[8];
    #pragma unroll
    for (int u = 0; u < 8; u++) {
        int unit = tid + u * 256;
        int isB = unit >> 10;
        int loc = unit & 1023;
        int row = loc >> 3, ucol = loc & 7;
        uOff[u] = swz128((uint32_t)(row * 128 + ucol * 16));
        uPtr[u] = x + ((size_t)b * SS + (isB ? t0 : s0) + row) * HH + ucol * 8;
    }

    // ---- prologue: chunk 0 into buf 0 ----
    {
        char* stgp = smem + SM_STAGE;
        #pragma unroll
        for (int u = 0; u < 4; u++) {
            float4 v0 = *(const float4*)(uPtr[u]);
            float4 v1 = *(const float4*)(uPtr[u] + 4);
            cvt_store_hi(stgp, A_HI, uOff[u], v0, v1);
        }
        if (!diag) {
            #pragma unroll
            for (int u = 4; u < 8; u++) {
                float4 v0 = *(const float4*)(uPtr[u]);
                float4 v1 = *(const float4*)(uPtr[u] + 4);
                cvt_store_hi(stgp, B_HI, uOff[u], v0, v1);
            }
        }
    }
    __syncthreads();

    for (int i = 0; i < NCHUNK; i++) {
        const uint32_t stg = sb + SM_STAGE + (uint32_t)(i & 1) * STAGE_BYTES;
        char* stgn = smem + SM_STAGE + ((i + 1) & 1) * STAGE_BYTES;
        const bool more = (i + 1 < NCHUNK);
        const int kn = (i + 1) * KC;

        float4 p0[4], p1[4];
        if (more) {
            #pragma unroll
            for (int u = 0; u < 4; u++) {
                p0[u] = *(const float4*)(uPtr[u] + kn);
                p1[u] = *(const float4*)(uPtr[u] + kn + 4);
            }
        }
        // ---- kk = 0, 1 ----
        #pragma unroll
        for (int kk = 0; kk < 2; kk++) {
            const uint32_t kb = kk * 32;
            uint32_t bh[2][4];
            #pragma unroll
            for (int nb = 0; nb < 2; nb++) {
                uint32_t roff = (uint32_t)((rB + nb * 16) * 128 + kb + kBe);
                ldmx4(bh[nb], stg + bBase + swz128(roff));
            }
            uint32_t ah[4][4];
            #pragma unroll
            for (int mi = 0; mi < 4; mi++) {
                uint32_t roff = (uint32_t)((rA + mi * 16) * 128 + kb + kAe);
                ldmx4(ah[mi], stg + A_HI + swz128(roff));
            }
            #pragma unroll
            for (int mi = 0; mi < 4; mi++)
                #pragma unroll
                for (int ni = 0; ni < 4; ni++)
                    mma16816(acc[mi][ni], ah[mi], &bh[ni >> 1][2 * (ni & 1)]);
        }
        if (more) {
            #pragma unroll
            for (int u = 0; u < 4; u++)
                cvt_store_hi(stgn, A_HI, uOff[u], p0[u], p1[u]);
            if (!diag) {
                #pragma unroll
                for (int u = 0; u < 4; u++) {
                    p0[u] = *(const float4*)(uPtr[u + 4] + kn);
                    p1[u] = *(const float4*)(uPtr[u + 4] + kn + 4);
                }
            }
        }
        // ---- kk = 2, 3 ----
        #pragma unroll
        for (int kk = 2; kk < 4; kk++) {
            const uint32_t kb = kk * 32;
            uint32_t bh[2][4];
            #pragma unroll
            for (int nb = 0; nb < 2; nb++) {
                uint32_t roff = (uint32_t)((rB + nb * 16) * 128 + kb + kBe);
                ldmx4(bh[nb], stg + bBase + swz128(roff));
            }
            uint32_t ah[4][4];
            #pragma unroll
            for (int mi = 0; mi < 4; mi++) {
                uint32_t roff = (uint32_t)((rA + mi * 16) * 128 + kb + kAe);
                ldmx4(ah[mi], stg + A_HI + swz128(roff));
            }
            #pragma unroll
            for (int mi = 0; mi < 4; mi++)
                #pragma unroll
                for (int ni = 0; ni < 4; ni++)
                    mma16816(acc[mi][ni], ah[mi], &bh[ni >> 1][2 * (ni & 1)]);
        }
        if (more && !diag) {
            #pragma unroll
            for (int u = 0; u < 4; u++)
                cvt_store_hi(stgn, B_HI, uOff[u + 4], p0[u], p1[u]);
        }
        __syncthreads();
    }

    // ---- epilogue: W[s][t] = coef*band*G into smem (overlay on stages) ----
    float* Wb = (float*)(smem + SM_STAGE);
    #pragma unroll
    for (int mi = 0; mi < 4; mi++) {
        int r0 = wm * 64 + mi * 16 + (lane >> 2);
        int r1 = r0 + 8;
        float mq0 = mqS[r0], ma0 = maS[r0], mn0 = mnS[r0];
        float mq1 = mqS[r1], ma1 = maS[r1], mn1 = mnS[r1];
        int tn0 = turnS[r0], tn1 = turnS[r1];
        #pragma unroll
        for (int ni = 0; ni < 4; ni++) {
            int tb0 = wn * 32 + ni * 8 + (lane & 3) * 2;
            #pragma unroll
            for (int e = 0; e < 4; e++) {
                int srow = (e >> 1) ? r1 : r0;
                int tcol = tb0 + (e & 1);
                float mq_ = (e >> 1) ? mq1 : mq0;
                float ma_ = (e >> 1) ? ma1 : ma0;
                float mn_ = (e >> 1) ? mn1 : mn0;
                int tn_ = (e >> 1) ? tn1 : tn0;
                int dt = turnT[tcol] - tn_;
                float coef = fmaf(mq_, wqT[tcol], fmaf(ma_, waT[tcol], mn_ * wnT[tcol]));
                float v = (dt >= -VR && dt <= VR) ? coef * acc[mi][ni][e] : 0.f;
                Wb[srow * WSTRIDE + tcol] = v;
            }
        }
    }
    __syncthreads();
    if (tid < 128) {
        float aq = 0.f, aa = 0.f, an = 0.f;
        #pragma unroll 4
        for (int s = 0; s < 128; s++) {
            float wv = Wb[s * WSTRIDE + tid];
            aq = fmaf(sWq[s], wv, aq);
            aa = fmaf(sWa[s], wv, aa);
            an = fmaf(sWn[s], wv, an);
        }
        atomicAdd(&g_alpha[0][b * SS + t0 + tid], aq);
        atomicAdd(&g_alpha[1][b * SS + t0 + tid], aa);
        atomicAdd(&g_alpha[2][b * SS + t0 + tid], an);
        if (!diag) {
            float bq = 0.f, ba = 0.f, bn = 0.f;
            #pragma unroll 4
            for (int t = 0; t < 128; t++) {
                float wv = Wb[tid * WSTRIDE + t];
                bq = fmaf(wqT[t], wv, bq);
                ba = fmaf(waT[t], wv, ba);
                bn = fmaf(wnT[t], wv, bn);
            }
            atomicAdd(&g_alpha[0][b * SS + s0 + tid], bq);
            atomicAdd(&g_alpha[1][b * SS + s0 + tid], ba);
            atomicAdd(&g_alpha[2][b * SS + s0 + tid], bn);
        }
    }
}

// ---------------------------------------------------------------------------
// Kernel 3: FUSED self + cross streaming pass, float4 per thread.
// grid (NB, SPLITS), 192 threads; thread t owns h = 4t..4t+3.
// ---------------------------------------------------------------------------
__global__ void __launch_bounds__(192) k3_fused(const float* __restrict__ x) {
    const int b = blockIdx.x;
    const int sc = blockIdx.y;
    const int sbase = sc * SCHUNK;
    const int tid = threadIdx.x;

    __shared__ float smq[SCHUNK], sma[SCHUNK], smn[SCHUNK];
    __shared__ float scq[SCHUNK], sca[SCHUNK], scn[SCHUNK];
    for (int s = tid; s < SCHUNK; s += 192) {
        int gs = b * SS + sbase + s;
        float mq = g_mask[0][gs], ma = g_mask[1][gs], mn = g_mask[2][gs];
        smq[s] = mq; sma[s] = ma; smn[s] = mn;
        scq[s] = mq * g_alpha[0][gs];
        sca[s] = ma * g_alpha[1][gs];
        scn[s] = mn * g_alpha[2][gs];
    }
    __syncthreads();

    float m0 = g_msum[0][b], m1 = g_msum[1][b], m2 = g_msum[2][b];
    float rsq = 1.f / (m0 + AVG_EPS_);
    float rsa = 1.f / (m1 + AVG_EPS_);
    float rsn = 1.f / (m2 + AVG_EPS_);
    float rcq = 1.f / (m1 + m2 + AVG_EPS_);
    float rca = 1.f / (m0 + m2 + AVG_EPS_);
    float rcn = 1.f / (m0 + m1 + AVG_EPS_);

    const float4* xb = (const float4*)(x + ((size_t)b * SS + sbase) * HH) + tid;
    float4 aq = {0,0,0,0}, aa = {0,0,0,0}, an = {0,0,0,0};
    float4 bq = {0,0,0,0}, ba = {0,0,0,0}, bn = {0,0,0,0};
    #pragma unroll 4
    for (int s = 0; s < SCHUNK; s++) {
        float4 v = xb[(size_t)s * (HH / 4)];
        float c;
        c = smq[s]; aq.x = fmaf(c, v.x, aq.x); aq.y = fmaf(c, v.y, aq.y); aq.z = fmaf(c, v.z, aq.z); aq.w = fmaf(c, v.w, aq.w);
        c = sma[s]; aa.x = fmaf(c, v.x, aa.x); aa.y = fmaf(c, v.y, aa.y); aa.z = fmaf(c, v.z, aa.z); aa.w = fmaf(c, v.w, aa.w);
        c = smn[s]; an.x = fmaf(c, v.x, an.x); an.y = fmaf(c, v.y, an.y); an.z = fmaf(c, v.z, an.z); an.w = fmaf(c, v.w, an.w);
        c = scq[s]; bq.x = fmaf(c, v.x, bq.x); bq.y = fmaf(c, v.y, bq.y); bq.z = fmaf(c, v.z, bq.z); bq.w = fmaf(c, v.w, bq.w);
        c = sca[s]; ba.x = fmaf(c, v.x, ba.x); ba.y = fmaf(c, v.y, ba.y); ba.z = fmaf(c, v.z, ba.z); ba.w = fmaf(c, v.w, ba.w);
        c = scn[s]; bn.x = fmaf(c, v.x, bn.x); bn.y = fmaf(c, v.y, bn.y); bn.z = fmaf(c, v.z, bn.z); bn.w = fmaf(c, v.w, bn.w);
    }
    const int h0 = b * HH + 4 * tid;
    atomicAdd(&g_self[0][h0 + 0], aq.x * rsq); atomicAdd(&g_self[0][h0 + 1], aq.y * rsq);
    atomicAdd(&g_self[0][h0 + 2], aq.z * rsq); atomicAdd(&g_self[0][h0 + 3], aq.w * rsq);
    atomicAdd(&g_self[1][h0 + 0], aa.x * rsa); atomicAdd(&g_self[1][h0 + 1], aa.y * rsa);
    atomicAdd(&g_self[1][h0 + 2], aa.z * rsa); atomicAdd(&g_self[1][h0 + 3], aa.w * rsa);
    atomicAdd(&g_self[2][h0 + 0], an.x * rsn); atomicAdd(&g_self[2][h0 + 1], an.y * rsn);
    atomicAdd(&g_self[2][h0 + 2], an.z * rsn); atomicAdd(&g_self[2][h0 + 3], an.w * rsn);
    atomicAdd(&g_cross[0][h0 + 0], bq.x * rcq); atomicAdd(&g_cross[0][h0 + 1], bq.y * rcq);
    atomicAdd(&g_cross[0][h0 + 2], bq.z * rcq); atomicAdd(&g_cross[0][h0 + 3], bq.w * rcq);
    atomicAdd(&g_cross[1][h0 + 0], ba.x * rca); atomicAdd(&g_cross[1][h0 + 1], ba.y * rca);
    atomicAdd(&g_cross[1][h0 + 2], ba.z * rca); atomicAdd(&g_cross[1][h0 + 3], ba.w * rca);
    atomicAdd(&g_cross[2][h0 + 0], bn.x * rcn); atomicAdd(&g_cross[2][h0 + 1], bn.y * rcn);
    atomicAdd(&g_cross[2][h0 + 2], bn.z * rcn); atomicAdd(&g_cross[2][h0 + 3], bn.w * rcn);
}

// ---------------------------------------------------------------------------
// Kernel 4: per-batch cosine logits; write q/a/n_output rows.
// ---------------------------------------------------------------------------
__global__ void k4_logits(float* __restrict__ out) {
    const int b = blockIdx.x;
    const int tid = threadIdx.x;
    float p[9];
    #pragma unroll
    for (int k = 0; k < 9; k++) p[k] = 0.f;
    for (int h = tid; h < HH; h += blockDim.x) {
        #pragma unroll
        for (int m = 0; m < 3; m++) {
            float sv = g_self[m][b * HH + h];
            float cv = g_cross[m][b * HH + h];
            p[m * 3 + 0] = fmaf(sv, cv, p[m * 3 + 0]);
            p[m * 3 + 1] = fmaf(sv, sv, p[m * 3 + 1]);
            p[m * 3 + 2] = fmaf(cv, cv, p[m * 3 + 2]);
        }
    }
    #pragma unroll
    for (int k = 0; k < 9; k++)
        #pragma unroll
        for (int o = 16; o > 0; o >>= 1)
            p[k] += __shfl_down_sync(0xffffffffu, p[k], o);
    __shared__ float red[9][8];
    if ((tid & 31) == 0) {
        int w = tid >> 5;
        #pragma unroll
        for (int k = 0; k < 9; k++) red[k][w] = p[k];
    }
    __syncthreads();
    if (tid == 0) {
        #pragma unroll
        for (int m = 0; m < 3; m++) {
            float dot = 0.f, n1 = 0.f, n2 = 0.f;
            for (int w = 0; w < 8; w++) {
                dot += red[m * 3 + 0][w];
                n1  += red[m * 3 + 1][w];
                n2  += red[m * 3 + 2][w];
            }
            float nx = fmaxf(sqrtf(n1), COS_EPS_);
            float ny = fmaxf(sqrtf(n2), COS_EPS_);
            float c = dot / (nx * ny);
            g_logits[m][b] = (c == 1.0f) ? __int_as_float(0x7fc00000) : c / TEMP_;
        }
    }
    if (b % SN == 0) {
        int g = b / SN;
        for (int h = tid; h < HH; h += blockDim.x) {
            out[1 + 0 * NG * HH + g * HH + h] = g_self[0][b * HH + h];
            out[1 + 1 * NG * HH + g * HH + h] = g_self[1][b * HH + h];
            out[1 + 2 * NG * HH + g * HH + h] = g_self[2][b * HH + h];
        }
    }
}

// ---------------------------------------------------------------------------
// Kernel 5: log-softmax + nanmean loss (tiny).
// ---------------------------------------------------------------------------
__global__ void k5_loss(const float* __restrict__ labels, float* __restrict__ out) {
    if (threadIdx.x != 0 || blockIdx.x != 0) return;
    float losses[3];
    for (int m = 0; m < 3; m++) {
        float sum = 0.f;
        int cnt = 0;
        for (int g = 0; g < NG; g++) {
            float l[SN];
            bool bad = false;
            for (int j = 0; j < SN; j++) {
                l[j] = g_logits[m][g * SN + j];
                if (isnan(l[j])) bad = true;
            }
            if (bad) continue;
            float mx = l[0];
            for (int j = 1; j < SN; j++) mx = fmaxf(mx, l[j]);
            float se = 0.f;
            for (int j = 0; j < SN; j++) se += expf(l[j] - mx);
            float lse = mx + logf(se);
            for (int j = 0; j < SN; j++) sum += (l[j] - lse) * labels[g * SN + j];
            cnt += SN;
        }
        losses[m] = -(sum / (float)cnt);
    }
    out[0] = (losses[1] + losses[0] + losses[2]) / 3.0f;
}

// ---------------------------------------------------------------------------
extern "C" void kernel_launch(void* const* d_in, const int* in_sizes, int n_in,
                              void* d_out, int out_size) {
    const float* x      = (const float*)d_in[0];
    const float* am     = (const float*)d_in[1];
    const float* labels = (const float*)d_in[2];
    const int*   qa     = (const int*)d_in[3];
    const int*   turn   = (const int*)d_in[4];
    float* out = (float*)d_out;

    cudaFuncSetAttribute(k2_mma, cudaFuncAttributeMaxDynamicSharedMemorySize, SMEM_BYTES);

    k0_masks<<<dim3(NB, 2), 256>>>(am, qa);
    k2_mma<<<dim3(SS / TN, SS / TM, NB), 256, SMEM_BYTES>>>(x, turn);
    k3_fused<<<dim3(NB, SPLITS), 192>>>(x);
    k4_logits<<<NB, 256>>>(out);
    k5_loss<<<1, 32>>>(labels, out);
}